// round 1
// baseline (speedup 1.0000x reference)
#include <cuda_runtime.h>
#include <math.h>

#define B_  64
#define S_  196
#define D_  2048
#define H_  8
#define DK_ 256
#define M_  16384
#define KSEL 32
#define C_  29

// ---------------- scratch (static device globals; no allocation) -------------
__device__ float g_xm[B_ * D_];
__device__ float g_xf[B_ * D_];
__device__ float g_q [B_ * D_];
__device__ float g_t [B_ * H_ * D_];
__device__ float g_u [B_ * H_ * D_];
__device__ float g_sc[B_ * H_ * M_];     // 32 MB
__device__ float g_z [B_ * H_ * D_];
__device__ float g_y [B_ * H_ * D_];
__device__ float g_attn[B_ * D_];
__device__ float g_resp[B_ * D_];
__device__ float g_fin [B_ * 2 * D_];
__device__ float g_fus [B_ * D_];

// ---------------- mean over S ------------------------------------------------
__global__ void mean_kernel(const float* __restrict__ x, float* __restrict__ xm) {
    int d = blockIdx.x * blockDim.x + threadIdx.x;   // 0..D_-1
    int b = blockIdx.y;
    const float* xp = x + (size_t)b * S_ * D_ + d;
    float s = 0.f;
    #pragma unroll 4
    for (int i = 0; i < S_; ++i) s += xp[(size_t)i * D_];
    xm[b * D_ + d] = s * (1.0f / S_);
}

// ---------------- generic tiled SGEMM ----------------------------------------
// C[M,N] = A[M,K] @ op(B) (+bias), op(B)=B[N,K]^T if TRANSB else B[K,N]
// z-batched via blockIdx.z with element strides. EPI: 0 none, 1 exact gelu.
template<int BM, int BN, int BK, int TM, int TN, bool TRANSB, int EPI>
__global__ void gemm_kernel(const float* __restrict__ A, int lda, long long sAz,
                            const float* __restrict__ B, int ldb, long long sBz,
                            float*       __restrict__ C, int ldc, long long sCz,
                            const float* __restrict__ bias, long long sbz,
                            int M, int N, int K)
{
    constexpr int THREADS = (BM / TM) * (BN / TN);
    __shared__ float As[BK][BM];
    __shared__ float Bs[BK][BN];

    A += blockIdx.z * sAz;
    B += blockIdx.z * sBz;
    C += blockIdx.z * sCz;
    const float* biasz = bias ? bias + blockIdx.z * sbz : nullptr;

    const int tid = threadIdx.x;
    const int m0 = blockIdx.y * BM;
    const int n0 = blockIdx.x * BN;
    const int tx = tid % (BN / TN);
    const int ty = tid / (BN / TN);

    float acc[TM][TN];
    #pragma unroll
    for (int i = 0; i < TM; ++i)
        #pragma unroll
        for (int j = 0; j < TN; ++j) acc[i][j] = 0.f;

    for (int k0 = 0; k0 < K; k0 += BK) {
        #pragma unroll
        for (int i = tid; i < BM * BK; i += THREADS) {
            int m = i / BK, k = i % BK;
            int gm = m0 + m;
            As[k][m] = (gm < M) ? A[(size_t)gm * lda + k0 + k] : 0.f;
        }
        if (TRANSB) {
            #pragma unroll
            for (int i = tid; i < BN * BK; i += THREADS) {
                int n = i / BK, k = i % BK;
                int gn = n0 + n;
                Bs[k][n] = (gn < N) ? B[(size_t)gn * ldb + k0 + k] : 0.f;
            }
        } else {
            #pragma unroll
            for (int i = tid; i < BN * BK; i += THREADS) {
                int k = i / BN, n = i % BN;
                int gn = n0 + n;
                Bs[k][n] = (gn < N) ? B[(size_t)(k0 + k) * ldb + gn] : 0.f;
            }
        }
        __syncthreads();

        #pragma unroll
        for (int k = 0; k < BK; ++k) {
            float a[TM], b[TN];
            #pragma unroll
            for (int i = 0; i < TM; ++i) a[i] = As[k][ty * TM + i];
            #pragma unroll
            for (int j = 0; j < TN; ++j) b[j] = Bs[k][tx * TN + j];
            #pragma unroll
            for (int i = 0; i < TM; ++i)
                #pragma unroll
                for (int j = 0; j < TN; ++j) acc[i][j] += a[i] * b[j];
        }
        __syncthreads();
    }

    #pragma unroll
    for (int i = 0; i < TM; ++i) {
        int gm = m0 + ty * TM + i;
        if (gm >= M) continue;
        #pragma unroll
        for (int j = 0; j < TN; ++j) {
            int gn = n0 + tx * TN + j;
            if (gn >= N) continue;
            float v = acc[i][j];
            if (biasz) v += biasz[gn];
            if (EPI == 1) v = 0.5f * v * (1.0f + erff(v * 0.70710678118654752f));
            C[(size_t)gm * ldc + gn] = v;
        }
    }
}

// ---------------- top-k(32) + softmax + weighted gather ----------------------
// One block per (b,h) row. scores row -> smem, 32x block argmax,
// p = softmax(sel/16), z = sum_k p_k * mem[idx_k].
__global__ void topk_z_kernel(const float* __restrict__ scores,
                              const float* __restrict__ mem,
                              float* __restrict__ z)
{
    extern __shared__ float sv[];                 // M_ floats
    __shared__ float rv[256];
    __shared__ int   ri[256];
    __shared__ float pk[KSEL];
    __shared__ int   pidx[KSEL];
    __shared__ float pw[KSEL];

    const int row = blockIdx.x;
    const int tid = threadIdx.x;
    const float* sr = scores + (size_t)row * M_;

    for (int i = tid; i < M_; i += 256) sv[i] = sr[i];
    __syncthreads();

    for (int sel = 0; sel < KSEL; ++sel) {
        float bm = -INFINITY; int bi = 0;
        for (int i = tid; i < M_; i += 256) {
            float v = sv[i];
            if (v > bm) { bm = v; bi = i; }
        }
        rv[tid] = bm; ri[tid] = bi;
        __syncthreads();
        for (int s = 128; s > 0; s >>= 1) {
            if (tid < s) {
                if (rv[tid + s] > rv[tid] ||
                    (rv[tid + s] == rv[tid] && ri[tid + s] < ri[tid])) {
                    rv[tid] = rv[tid + s]; ri[tid] = ri[tid + s];
                }
            }
            __syncthreads();
        }
        if (tid == 0) { pk[sel] = rv[0]; pidx[sel] = ri[0]; sv[ri[0]] = -INFINITY; }
        __syncthreads();
    }

    if (tid == 0) {
        // scores were computed WITHOUT the /sqrt(DK): apply 1/16 here.
        float mx = pk[0], s = 0.f;
        for (int k = 0; k < KSEL; ++k) { float e = expf((pk[k] - mx) * 0.0625f); pw[k] = e; s += e; }
        float inv = 1.f / s;
        for (int k = 0; k < KSEL; ++k) pw[k] *= inv;
    }
    __syncthreads();

    for (int d = tid; d < D_; d += 256) {
        float acc = 0.f;
        #pragma unroll
        for (int k = 0; k < KSEL; ++k) acc += pw[k] * mem[(size_t)pidx[k] * D_ + d];
        z[(size_t)row * D_ + d] = acc;
    }
}

// ---------------- concat [xf | resp] -----------------------------------------
__global__ void concat_kernel(const float* __restrict__ xf,
                              const float* __restrict__ resp,
                              float* __restrict__ fin)
{
    int i = blockIdx.x * blockDim.x + threadIdx.x;   // B_*D_
    int b = i / D_, d = i % D_;
    fin[(size_t)b * 2 * D_ + d]      = xf[i];
    fin[(size_t)b * 2 * D_ + D_ + d] = resp[i];
}

// ---------------- launch ------------------------------------------------------
extern "C" void kernel_launch(void* const* d_in, const int* in_sizes, int n_in,
                              void* d_out, int out_size)
{
    const float* x      = (const float*)d_in[0];
    // d_in[1] = box_masks (unused by reference)
    const float* mem    = (const float*)d_in[2];
    const float* ff_w   = (const float*)d_in[3];
    const float* ff_b   = (const float*)d_in[4];
    const float* mp_w   = (const float*)d_in[5];
    const float* mp_b   = (const float*)d_in[6];
    const float* wq     = (const float*)d_in[7];
    const float* bq     = (const float*)d_in[8];
    const float* wk     = (const float*)d_in[9];
    // d_in[10] = bk (cancels: per-row constant shift is invariant under top-k & softmax)
    const float* wv     = (const float*)d_in[11];
    const float* bv     = (const float*)d_in[12];
    const float* wo     = (const float*)d_in[13];
    const float* bo     = (const float*)d_in[14];
    const float* fuse_w = (const float*)d_in[15];
    const float* fuse_b = (const float*)d_in[16];
    const float* head_w = (const float*)d_in[17];
    const float* head_b = (const float*)d_in[18];
    float* out = (float*)d_out;

    float *xm, *xf, *q, *t, *u, *sc, *z, *y, *attn, *resp, *fin, *fus;
    cudaGetSymbolAddress((void**)&xm,   g_xm);
    cudaGetSymbolAddress((void**)&xf,   g_xf);
    cudaGetSymbolAddress((void**)&q,    g_q);
    cudaGetSymbolAddress((void**)&t,    g_t);
    cudaGetSymbolAddress((void**)&u,    g_u);
    cudaGetSymbolAddress((void**)&sc,   g_sc);
    cudaGetSymbolAddress((void**)&z,    g_z);
    cudaGetSymbolAddress((void**)&y,    g_y);
    cudaGetSymbolAddress((void**)&attn, g_attn);
    cudaGetSymbolAddress((void**)&resp, g_resp);
    cudaGetSymbolAddress((void**)&fin,  g_fin);
    cudaGetSymbolAddress((void**)&fus,  g_fus);

    cudaFuncSetAttribute(topk_z_kernel,
                         cudaFuncAttributeMaxDynamicSharedMemorySize, M_ * sizeof(float));

    // 1) xm = mean_s(x)
    mean_kernel<<<dim3(D_ / 256, B_), 256>>>(x, xm);

    // 2) xf = xm @ ff_w.T + ff_b           [64,2048] K=2048
    gemm_kernel<64,64,16,4,4,true,0><<<dim3(D_/64, 1, 1), 256>>>(
        xm, D_, 0, ff_w, D_, 0, xf, D_, 0, ff_b, 0, B_, D_, D_);

    // 3) q = xf @ wq.T + bq                [64,2048]
    gemm_kernel<64,64,16,4,4,true,0><<<dim3(D_/64, 1, 1), 256>>>(
        xf, D_, 0, wq, D_, 0, q, D_, 0, bq, 0, B_, D_, D_);

    // 4) t[b*8+h, :] = q_h[b] @ wk_h       per-head: M=64,K=256,N=2048
    gemm_kernel<64,64,16,4,4,false,0><<<dim3(D_/64, 1, H_), 256>>>(
        q, D_, DK_, wk, D_, (long long)DK_ * D_, t, H_ * D_, D_,
        nullptr, 0, B_, D_, DK_);

    // 5) u = t @ memproj_w                 [512,2048] K=2048
    gemm_kernel<64,64,16,4,4,false,0><<<dim3(D_/64, (B_*H_)/64, 1), 256>>>(
        t, D_, 0, mp_w, D_, 0, u, D_, 0, nullptr, 0, B_ * H_, D_, D_);

    // 6) scores = u @ mem.T                [512,16384] K=2048  (big one)
    gemm_kernel<128,128,8,8,8,true,0><<<dim3(M_/128, (B_*H_)/128, 1), 256>>>(
        u, D_, 0, mem, D_, 0, sc, M_, 0, nullptr, 0, B_ * H_, M_, D_);

    // 7) top-32 + softmax + z gather
    topk_z_kernel<<<B_ * H_, 256, M_ * sizeof(float)>>>(sc, mem, z);

    // 8) y = z @ memproj_w.T + memproj_b   [512,2048] K=2048
    gemm_kernel<64,64,16,4,4,true,0><<<dim3(D_/64, (B_*H_)/64, 1), 256>>>(
        z, D_, 0, mp_w, D_, 0, y, D_, 0, mp_b, 0, B_ * H_, D_, D_);

    // 9) attn[b, h*256+e] = y_h[b] @ wv_h.T + bv_h   per-head: M=64,N=256,K=2048
    gemm_kernel<64,64,16,4,4,true,0><<<dim3(DK_/64, 1, H_), 256>>>(
        y, H_ * D_, D_, wv, D_, (long long)DK_ * D_, attn, D_, DK_,
        bv, DK_, B_, DK_, D_);

    // 10) resp = attn @ wo.T + bo          [64,2048]
    gemm_kernel<64,64,16,4,4,true,0><<<dim3(D_/64, 1, 1), 256>>>(
        attn, D_, 0, wo, D_, 0, resp, D_, 0, bo, 0, B_, D_, D_);

    // 11) fin = [xf | resp]
    concat_kernel<<<(B_ * D_) / 256, 256>>>(xf, resp, fin);

    // 12) fus = gelu(fin @ fuse_w.T + fuse_b)   [64,2048] K=4096
    gemm_kernel<64,64,16,4,4,true,1><<<dim3(D_/64, 1, 1), 256>>>(
        fin, 2 * D_, 0, fuse_w, 2 * D_, 0, fus, D_, 0, fuse_b, 0, B_, D_, 2 * D_);

    // 13) logits = fus @ head_w.T + head_b  [64,29] K=2048
    gemm_kernel<64,64,16,4,4,true,0><<<dim3(1, 1, 1), 256>>>(
        fus, D_, 0, head_w, D_, 0, out, C_, 0, head_b, 0, B_, C_, D_);
}

// round 2
// speedup vs baseline: 4.4966x; 4.4966x over previous
#include <cuda_runtime.h>
#include <cuda_bf16.h>
#include <math.h>

#define B_  64
#define S_  196
#define D_  2048
#define H_  8
#define DK_ 256
#define M_  16384
#define KSEL 32
#define C_  29

// ---------------- scratch (static device globals; no allocation) -------------
__device__ float g_xm[B_ * D_];
__device__ float g_xf[B_ * D_];
__device__ float g_q [B_ * D_];
__device__ float g_t [B_ * H_ * D_];
__device__ float g_u [B_ * H_ * D_];
__device__ float g_sc[B_ * H_ * M_];               // 32 MB
__device__ float g_z [B_ * H_ * D_];
__device__ float g_y [B_ * H_ * D_];
__device__ float g_attn[B_ * D_];
__device__ float g_resp[B_ * D_];
__device__ float g_fin [B_ * 2 * D_];
__device__ float g_fus [B_ * D_];
__device__ float g_part[4 * 512 * 2048];           // 16 MB split-K partials

__device__ __nv_bfloat16 g_mem_bf[M_ * D_];        // 64 MB
__device__ __nv_bfloat16 g_mpw_bf[D_ * D_];
__device__ __nv_bfloat16 g_wv_bf [D_ * D_];
__device__ __nv_bfloat16 g_wo_bf [D_ * D_];
__device__ __nv_bfloat16 g_u_bf  [B_ * H_ * D_];
__device__ __nv_bfloat16 g_z_bf  [B_ * H_ * D_];
__device__ __nv_bfloat16 g_y_bf  [B_ * H_ * D_];
__device__ __nv_bfloat16 g_attn_bf[B_ * D_];

// ---------------- mean over S ------------------------------------------------
__global__ void mean_kernel(const float* __restrict__ x, float* __restrict__ xm) {
    int d = blockIdx.x * blockDim.x + threadIdx.x;
    int b = blockIdx.y;
    const float* xp = x + (size_t)b * S_ * D_ + d;
    float s = 0.f;
    #pragma unroll 4
    for (int i = 0; i < S_; ++i) s += xp[(size_t)i * D_];
    xm[b * D_ + d] = s * (1.0f / S_);
}

// ---------------- fp32 -> bf16 convert ---------------------------------------
__global__ void f2b_kernel(const float* __restrict__ a, __nv_bfloat16* __restrict__ o, int n) {
    int i = (blockIdx.x * blockDim.x + threadIdx.x) * 4;
    if (i < n) {
        float4 v = *(const float4*)(a + i);
        __nv_bfloat162 p0 = __floats2bfloat162_rn(v.x, v.y);
        __nv_bfloat162 p1 = __floats2bfloat162_rn(v.z, v.w);
        *(__nv_bfloat162*)(o + i)     = p0;
        *(__nv_bfloat162*)(o + i + 2) = p1;
    }
}

// ---------------- fp32 tiled SGEMM with optional split-K ----------------------
// C[M,N] = A[M,K] @ op(B) (+bias if SPLIT==1), op(B)=B[N,K]^T if TRANSB.
// blockIdx.z = batch * SPLIT + split. When SPLIT>1 caller points C at partials
// (ldc=N, sCz=M*N) and passes bias=nullptr; reduce_kernel finishes.
template<int BM, int BN, int BK, int TM, int TN, bool TRANSB, int EPI, int SPLIT>
__global__ void gemm_kernel(const float* __restrict__ A, int lda, long long sAz,
                            const float* __restrict__ B, int ldb, long long sBz,
                            float*       __restrict__ C, int ldc, long long sCz,
                            const float* __restrict__ bias, long long sbz,
                            int M, int N, int K)
{
    constexpr int THREADS = (BM / TM) * (BN / TN);
    __shared__ float As[BK][BM];
    __shared__ float Bs[BK][BN];

    const int zb = blockIdx.z / SPLIT;
    A += zb * sAz;
    B += zb * sBz;
    C += (size_t)blockIdx.z * sCz;
    const float* biasz = bias ? bias + zb * sbz : nullptr;
    const int Kc = K / SPLIT;
    const int koff = (blockIdx.z % SPLIT) * Kc;

    const int tid = threadIdx.x;
    const int m0 = blockIdx.y * BM;
    const int n0 = blockIdx.x * BN;
    const int tx = tid % (BN / TN);
    const int ty = tid / (BN / TN);

    float acc[TM][TN];
    #pragma unroll
    for (int i = 0; i < TM; ++i)
        #pragma unroll
        for (int j = 0; j < TN; ++j) acc[i][j] = 0.f;

    for (int k0 = koff; k0 < koff + Kc; k0 += BK) {
        #pragma unroll
        for (int i = tid; i < BM * BK; i += THREADS) {
            int m = i / BK, k = i % BK;
            int gm = m0 + m;
            As[k][m] = (gm < M) ? A[(size_t)gm * lda + k0 + k] : 0.f;
        }
        if (TRANSB) {
            #pragma unroll
            for (int i = tid; i < BN * BK; i += THREADS) {
                int n = i / BK, k = i % BK;
                int gn = n0 + n;
                Bs[k][n] = (gn < N) ? B[(size_t)gn * ldb + k0 + k] : 0.f;
            }
        } else {
            #pragma unroll
            for (int i = tid; i < BN * BK; i += THREADS) {
                int k = i / BN, n = i % BN;
                int gn = n0 + n;
                Bs[k][n] = (gn < N) ? B[(size_t)(k0 + k) * ldb + gn] : 0.f;
            }
        }
        __syncthreads();

        #pragma unroll
        for (int k = 0; k < BK; ++k) {
            float a[TM], b[TN];
            #pragma unroll
            for (int i = 0; i < TM; ++i) a[i] = As[k][ty * TM + i];
            #pragma unroll
            for (int j = 0; j < TN; ++j) b[j] = Bs[k][tx * TN + j];
            #pragma unroll
            for (int i = 0; i < TM; ++i)
                #pragma unroll
                for (int j = 0; j < TN; ++j) acc[i][j] += a[i] * b[j];
        }
        __syncthreads();
    }

    #pragma unroll
    for (int i = 0; i < TM; ++i) {
        int gm = m0 + ty * TM + i;
        if (gm >= M) continue;
        #pragma unroll
        for (int j = 0; j < TN; ++j) {
            int gn = n0 + tx * TN + j;
            if (gn >= N) continue;
            float v = acc[i][j];
            if (biasz) v += biasz[gn];
            if (EPI == 1) v = 0.5f * v * (1.0f + erff(v * 0.70710678118654752f));
            C[(size_t)gm * ldc + gn] = v;
        }
    }
}

// ---------------- split-K reduce ----------------------------------------------
template<int EPI>
__global__ void reduce_kernel(const float* __restrict__ part, float* __restrict__ C,
                              int ldc, long long sCz,
                              const float* __restrict__ bias, long long sbz,
                              int MN, int N, int SPLIT)
{
    int i = blockIdx.x * 256 + threadIdx.x;
    int z = blockIdx.y;
    if (i >= MN) return;
    const float* p = part + (size_t)z * SPLIT * MN + i;
    float s = 0.f;
    for (int k = 0; k < SPLIT; ++k) s += p[(size_t)k * MN];
    int n = i % N;
    if (bias) s += bias[z * sbz + n];
    if (EPI == 1) s = 0.5f * s * (1.0f + erff(s * 0.70710678118654752f));
    C[(size_t)z * sCz + (size_t)(i / N) * ldc + n] = s;
}

// ---------------- bf16 tensor-core TN GEMM ------------------------------------
// C[M,N](fp32) = A[M,K](bf16, K-major) @ B[N,K](bf16, K-major)^T (+bias)
// 128x128x64 tiles, 8 warps (4x2), cp.async double buffer, swizzled smem.
// Requires K%64==0, N%128==0; M guarded.
__device__ __forceinline__ unsigned bswz(int row, int chunk) {
    return (unsigned)(row * 64 + ((chunk ^ (row & 7)) * 8));   // bf16 elements
}

#define LDSM4(R, ADDR) asm volatile( \
    "ldmatrix.sync.aligned.m8n8.x4.shared.b16 {%0,%1,%2,%3}, [%4];" \
    : "=r"((R)[0]), "=r"((R)[1]), "=r"((R)[2]), "=r"((R)[3]) : "r"(ADDR))

#define MMA16816(D, A, B0, B1) asm volatile( \
    "mma.sync.aligned.m16n8k16.row.col.f32.bf16.bf16.f32 " \
    "{%0,%1,%2,%3},{%4,%5,%6,%7},{%8,%9},{%0,%1,%2,%3};" \
    : "+f"((D)[0]), "+f"((D)[1]), "+f"((D)[2]), "+f"((D)[3]) \
    : "r"((A)[0]), "r"((A)[1]), "r"((A)[2]), "r"((A)[3]), "r"(B0), "r"(B1))

template<bool HAS_BIAS>
__global__ __launch_bounds__(256) void bgemm_kernel(
    const __nv_bfloat16* __restrict__ A, int lda, long long sAz,
    const __nv_bfloat16* __restrict__ B, int ldb, long long sBz,
    float* __restrict__ C, int ldc, long long sCz,
    const float* __restrict__ bias, long long sbz,
    int M, int N, int K)
{
    extern __shared__ __nv_bfloat16 sm[];   // 2 stages * (A 8192 + B 8192) bf16
    const int tid  = threadIdx.x;
    const int lane = tid & 31;
    const int warp = tid >> 5;
    const int warpM = (warp >> 1) * 32;
    const int warpN = (warp & 1) * 64;
    const int m0 = blockIdx.y * 128;
    const int n0 = blockIdx.x * 128;
    const int z  = blockIdx.z;

    A += (size_t)z * sAz;
    B += (size_t)z * sBz;
    C += (size_t)z * sCz;

    unsigned sbase = (unsigned)__cvta_generic_to_shared(sm);

    float acc[2][8][4];
    #pragma unroll
    for (int a = 0; a < 2; ++a)
        #pragma unroll
        for (int b = 0; b < 8; ++b)
            #pragma unroll
            for (int c = 0; c < 4; ++c) acc[a][b][c] = 0.f;

    const int cidx = tid & 7;               // chunk column for loads
    const int rbase = tid >> 3;             // 0..31

    auto load_stage = [&](int s, int k0) {
        unsigned aB = sbase + (unsigned)s * 32768u;
        unsigned bB = aB + 16384u;
        #pragma unroll
        for (int j = 0; j < 4; ++j) {
            int r = j * 32 + rbase;
            const __nv_bfloat16* srcA = A + (size_t)(m0 + r) * lda + k0 + cidx * 8;
            unsigned dstA = aB + bswz(r, cidx) * 2u;
            int szA = (m0 + r < M) ? 16 : 0;
            asm volatile("cp.async.cg.shared.global [%0], [%1], 16, %2;\n"
                         :: "r"(dstA), "l"(srcA), "r"(szA));
            const __nv_bfloat16* srcB = B + (size_t)(n0 + r) * ldb + k0 + cidx * 8;
            unsigned dstB = bB + bswz(r, cidx) * 2u;
            asm volatile("cp.async.cg.shared.global [%0], [%1], 16, 16;\n"
                         :: "r"(dstB), "l"(srcB));
        }
    };

    auto compute = [&](int s) {
        unsigned aB = sbase + (unsigned)s * 32768u;
        unsigned bB = aB + 16384u;
        #pragma unroll
        for (int kk = 0; kk < 64; kk += 16) {
            unsigned af[2][4];
            #pragma unroll
            for (int mi = 0; mi < 2; ++mi) {
                int row = warpM + mi * 16 + (lane & 15);
                int ch  = (kk >> 3) + (lane >> 4);
                unsigned addr = aB + bswz(row, ch) * 2u;
                LDSM4(af[mi], addr);
            }
            unsigned bf[4][4];
            #pragma unroll
            for (int ni = 0; ni < 4; ++ni) {
                int g = lane >> 3;
                int row = warpN + ni * 16 + ((g >> 1) << 3) + (lane & 7);
                int ch  = (kk >> 3) + (g & 1);
                unsigned addr = bB + bswz(row, ch) * 2u;
                LDSM4(bf[ni], addr);
            }
            #pragma unroll
            for (int mi = 0; mi < 2; ++mi)
                #pragma unroll
                for (int n8 = 0; n8 < 8; ++n8) {
                    unsigned* bb = &bf[n8 >> 1][(n8 & 1) * 2];
                    MMA16816(acc[mi][n8], af[mi], bb[0], bb[1]);
                }
        }
    };

    const int KT = K >> 6;
    load_stage(0, 0);
    asm volatile("cp.async.commit_group;\n" ::);
    for (int t = 0; t < KT; ++t) {
        if (t + 1 < KT) {
            load_stage((t + 1) & 1, (t + 1) << 6);
            asm volatile("cp.async.commit_group;\n" ::);
            asm volatile("cp.async.wait_group 1;\n" ::);
        } else {
            asm volatile("cp.async.wait_group 0;\n" ::);
        }
        __syncthreads();
        compute(t & 1);
        __syncthreads();
    }

    // epilogue
    #pragma unroll
    for (int mi = 0; mi < 2; ++mi) {
        int row = m0 + warpM + mi * 16 + (lane >> 2);
        #pragma unroll
        for (int n8 = 0; n8 < 8; ++n8) {
            int col = n0 + warpN + n8 * 8 + (lane & 3) * 2;
            float b0 = 0.f, b1 = 0.f;
            if (HAS_BIAS) {
                b0 = bias[z * sbz + col];
                b1 = bias[z * sbz + col + 1];
            }
            if (row < M) {
                float2 v = make_float2(acc[mi][n8][0] + b0, acc[mi][n8][1] + b1);
                *(float2*)(C + (size_t)row * ldc + col) = v;
            }
            if (row + 8 < M) {
                float2 v = make_float2(acc[mi][n8][2] + b0, acc[mi][n8][3] + b1);
                *(float2*)(C + (size_t)(row + 8) * ldc + col) = v;
            }
        }
    }
}

// ---------------- top-64 coarse -> exact fp32 rescore -> top-32 + z ----------
__global__ __launch_bounds__(256) void topk_kernel(
    const float* __restrict__ scores, const float* __restrict__ u,
    const float* __restrict__ mem, float* __restrict__ z,
    __nv_bfloat16* __restrict__ zbf)
{
    extern __shared__ float dyn[];
    float* sv = dyn;            // M_
    float* us = dyn + M_;       // D_
    __shared__ float warpv[8];
    __shared__ int   warpi[8];
    __shared__ int   s_wini;
    __shared__ int   cand[64];
    __shared__ float scE[64];
    __shared__ float pw[KSEL];
    __shared__ int   pidx[KSEL];

    const int row = blockIdx.x;
    const int tid = threadIdx.x;
    const int lane = tid & 31;
    const int warp = tid >> 5;
    const float* sr = scores + (size_t)row * M_;
    const float* ur = u + (size_t)row * D_;

    // load row into smem; per-thread cached argmax over strided slice
    float bv = -INFINITY; int bi = 0;
    #pragma unroll 4
    for (int j = 0; j < M_ / 256; ++j) {
        int i = tid + j * 256;
        float v = sr[i];
        sv[i] = v;
        if (v > bv) { bv = v; bi = i; }
    }
    for (int j = tid; j < D_; j += 256) us[j] = ur[j];
    __syncthreads();

    // coarse top-64 (value desc, lower index wins ties)
    for (int sel = 0; sel < 64; ++sel) {
        float v = bv; int ix = bi;
        #pragma unroll
        for (int o = 16; o > 0; o >>= 1) {
            float v2 = __shfl_down_sync(0xffffffffu, v, o);
            int   i2 = __shfl_down_sync(0xffffffffu, ix, o);
            if (v2 > v || (v2 == v && i2 < ix)) { v = v2; ix = i2; }
        }
        if (lane == 0) { warpv[warp] = v; warpi[warp] = ix; }
        __syncthreads();
        if (warp == 0) {
            float v3 = (lane < 8) ? warpv[lane] : -INFINITY;
            int   i3 = (lane < 8) ? warpi[lane] : 0x7fffffff;
            #pragma unroll
            for (int o = 4; o > 0; o >>= 1) {
                float v2 = __shfl_down_sync(0xffffffffu, v3, o);
                int   i2 = __shfl_down_sync(0xffffffffu, i3, o);
                if (v2 > v3 || (v2 == v3 && i2 < i3)) { v3 = v2; i3 = i2; }
            }
            if (lane == 0) { s_wini = i3; cand[sel] = i3; }
        }
        __syncthreads();
        int w = s_wini;
        if ((w & 255) == tid) {
            sv[w] = -INFINITY;
            bv = -INFINITY; bi = 0;
            #pragma unroll 4
            for (int j = 0; j < M_ / 256; ++j) {
                int i = tid + j * 256;
                float vv = sv[i];
                if (vv > bv) { bv = vv; bi = i; }
            }
        }
        __syncthreads();
    }

    // exact fp32 rescore of 64 candidates
    for (int r8 = 0; r8 < 8; ++r8) {
        int c = r8 * 8 + warp;
        const float* mr = mem + (size_t)cand[c] * D_;
        float s = 0.f;
        #pragma unroll 8
        for (int j = lane; j < D_; j += 32) s += us[j] * mr[j];
        #pragma unroll
        for (int o = 16; o > 0; o >>= 1) s += __shfl_down_sync(0xffffffffu, s, o);
        if (lane == 0) scE[c] = s;
    }
    __syncthreads();

    // exact top-32 of the 64 (warp 0), then softmax(sel/16)
    if (warp == 0) {
        float v0 = scE[lane],      v1 = scE[32 + lane];
        int   i0 = cand[lane],     i1 = cand[32 + lane];
        for (int s = 0; s < KSEL; ++s) {
            float v; int ix, slot;
            if (v0 > v1 || (v0 == v1 && i0 < i1)) { v = v0; ix = i0; slot = lane; }
            else                                  { v = v1; ix = i1; slot = 32 + lane; }
            #pragma unroll
            for (int o = 16; o > 0; o >>= 1) {
                float v2 = __shfl_down_sync(0xffffffffu, v, o);
                int   x2 = __shfl_down_sync(0xffffffffu, ix, o);
                int   s2 = __shfl_down_sync(0xffffffffu, slot, o);
                if (v2 > v || (v2 == v && x2 < ix)) { v = v2; ix = x2; slot = s2; }
            }
            v    = __shfl_sync(0xffffffffu, v, 0);
            ix   = __shfl_sync(0xffffffffu, ix, 0);
            slot = __shfl_sync(0xffffffffu, slot, 0);
            if (slot == lane)      v0 = -INFINITY;
            if (slot == 32 + lane) v1 = -INFINITY;
            if (lane == 0) { pw[s] = v; pidx[s] = ix; }
        }
        if (lane == 0) {
            float mx = pw[0], ssum = 0.f;
            for (int k = 0; k < KSEL; ++k) {
                float e = expf((pw[k] - mx) * 0.0625f);
                pw[k] = e; ssum += e;
            }
            float inv = 1.f / ssum;
            for (int k = 0; k < KSEL; ++k) pw[k] *= inv;
        }
    }
    __syncthreads();

    // z = sum_k p_k * mem[idx_k]
    for (int d = tid; d < D_; d += 256) {
        float acc = 0.f;
        #pragma unroll
        for (int k = 0; k < KSEL; ++k) acc += pw[k] * mem[(size_t)pidx[k] * D_ + d];
        z[(size_t)row * D_ + d] = acc;
        zbf[(size_t)row * D_ + d] = __float2bfloat16(acc);
    }
}

// ---------------- concat [xf | resp] ------------------------------------------
__global__ void concat_kernel(const float* __restrict__ xf,
                              const float* __restrict__ resp,
                              float* __restrict__ fin)
{
    int i = blockIdx.x * blockDim.x + threadIdx.x;
    int b = i / D_, d = i % D_;
    fin[(size_t)b * 2 * D_ + d]      = xf[i];
    fin[(size_t)b * 2 * D_ + D_ + d] = resp[i];
}

// ---------------- launch -------------------------------------------------------
extern "C" void kernel_launch(void* const* d_in, const int* in_sizes, int n_in,
                              void* d_out, int out_size)
{
    const float* x      = (const float*)d_in[0];
    const float* mem    = (const float*)d_in[2];
    const float* ff_w   = (const float*)d_in[3];
    const float* ff_b   = (const float*)d_in[4];
    const float* mp_w   = (const float*)d_in[5];
    const float* mp_b   = (const float*)d_in[6];
    const float* wq     = (const float*)d_in[7];
    const float* bq     = (const float*)d_in[8];
    const float* wk     = (const float*)d_in[9];
    const float* wv     = (const float*)d_in[11];
    const float* bv     = (const float*)d_in[12];
    const float* wo     = (const float*)d_in[13];
    const float* bo     = (const float*)d_in[14];
    const float* fuse_w = (const float*)d_in[15];
    const float* fuse_b = (const float*)d_in[16];
    const float* head_w = (const float*)d_in[17];
    const float* head_b = (const float*)d_in[18];
    float* out = (float*)d_out;

    float *xm, *xf, *q, *t, *u, *sc, *z, *y, *attn, *resp, *fin, *fus, *part;
    __nv_bfloat16 *mem_bf, *mpw_bf, *wv_bf, *wo_bf, *u_bf, *z_bf, *y_bf, *attn_bf;
    cudaGetSymbolAddress((void**)&xm,   g_xm);
    cudaGetSymbolAddress((void**)&xf,   g_xf);
    cudaGetSymbolAddress((void**)&q,    g_q);
    cudaGetSymbolAddress((void**)&t,    g_t);
    cudaGetSymbolAddress((void**)&u,    g_u);
    cudaGetSymbolAddress((void**)&sc,   g_sc);
    cudaGetSymbolAddress((void**)&z,    g_z);
    cudaGetSymbolAddress((void**)&y,    g_y);
    cudaGetSymbolAddress((void**)&attn, g_attn);
    cudaGetSymbolAddress((void**)&resp, g_resp);
    cudaGetSymbolAddress((void**)&fin,  g_fin);
    cudaGetSymbolAddress((void**)&fus,  g_fus);
    cudaGetSymbolAddress((void**)&part, g_part);
    cudaGetSymbolAddress((void**)&mem_bf,  g_mem_bf);
    cudaGetSymbolAddress((void**)&mpw_bf,  g_mpw_bf);
    cudaGetSymbolAddress((void**)&wv_bf,   g_wv_bf);
    cudaGetSymbolAddress((void**)&wo_bf,   g_wo_bf);
    cudaGetSymbolAddress((void**)&u_bf,    g_u_bf);
    cudaGetSymbolAddress((void**)&z_bf,    g_z_bf);
    cudaGetSymbolAddress((void**)&y_bf,    g_y_bf);
    cudaGetSymbolAddress((void**)&attn_bf, g_attn_bf);

    cudaFuncSetAttribute(bgemm_kernel<false>,
                         cudaFuncAttributeMaxDynamicSharedMemorySize, 65536);
    cudaFuncSetAttribute(bgemm_kernel<true>,
                         cudaFuncAttributeMaxDynamicSharedMemorySize, 65536);
    cudaFuncSetAttribute(topk_kernel,
                         cudaFuncAttributeMaxDynamicSharedMemorySize, (M_ + D_) * 4);

    // weight conversions (deterministic; replayed each graph launch)
    f2b_kernel<<<(M_ * D_ / 4 + 255) / 256, 256>>>(mem, mem_bf, M_ * D_);
    f2b_kernel<<<(D_ * D_ / 4 + 255) / 256, 256>>>(mp_w, mpw_bf, D_ * D_);
    f2b_kernel<<<(D_ * D_ / 4 + 255) / 256, 256>>>(wv, wv_bf, D_ * D_);
    f2b_kernel<<<(D_ * D_ / 4 + 255) / 256, 256>>>(wo, wo_bf, D_ * D_);

    // 1) xm = mean_s(x)
    mean_kernel<<<dim3(D_ / 256, B_), 256>>>(x, xm);

    // 2) xf = xm @ ff_w.T + ff_b   (fp32, split-K 8)
    gemm_kernel<64,128,16,4,8,true,0,8><<<dim3(16, 1, 8), 256>>>(
        xm, D_, 0, ff_w, D_, 0, part, D_, (long long)B_ * D_, nullptr, 0, B_, D_, D_);
    reduce_kernel<0><<<dim3(B_ * D_ / 256, 1), 256>>>(
        part, xf, D_, 0, ff_b, 0, B_ * D_, D_, 8);

    // 3) q = xf @ wq.T + bq        (fp32, split-K 8)
    gemm_kernel<64,128,16,4,8,true,0,8><<<dim3(16, 1, 8), 256>>>(
        xf, D_, 0, wq, D_, 0, part, D_, (long long)B_ * D_, nullptr, 0, B_, D_, D_);
    reduce_kernel<0><<<dim3(B_ * D_ / 256, 1), 256>>>(
        part, q, D_, 0, bq, 0, B_ * D_, D_, 8);

    // 4) t[b*8+h] = q_h[b] @ wk_h  (fp32, batched over heads)
    gemm_kernel<64,128,16,4,8,false,0,1><<<dim3(16, 1, H_), 256>>>(
        q, D_, DK_, wk, D_, (long long)DK_ * D_, t, H_ * D_, D_,
        nullptr, 0, B_, D_, DK_);

    // 5) u = t @ memproj_w         (fp32, split-K 4)
    gemm_kernel<128,128,8,8,8,false,0,4><<<dim3(16, 4, 4), 256>>>(
        t, D_, 0, mp_w, D_, 0, part, D_, (long long)B_ * H_ * D_,
        nullptr, 0, B_ * H_, D_, D_);
    reduce_kernel<0><<<dim3(B_ * H_ * D_ / 256, 1), 256>>>(
        part, u, D_, 0, nullptr, 0, B_ * H_ * D_, D_, 4);

    f2b_kernel<<<(B_ * H_ * D_ / 4 + 255) / 256, 256>>>(u, u_bf, B_ * H_ * D_);

    // 6) scores = u @ mem.T        (bf16 tensor cores, fp32 accum)
    bgemm_kernel<false><<<dim3(M_ / 128, (B_ * H_) / 128, 1), 256, 65536>>>(
        u_bf, D_, 0, mem_bf, D_, 0, sc, M_, 0, nullptr, 0, B_ * H_, M_, D_);

    // 7) coarse top-64 -> exact rescore -> top-32 -> softmax -> z
    topk_kernel<<<B_ * H_, 256, (M_ + D_) * 4>>>(sc, u, mem, z, z_bf);

    // 8) y = z @ memproj_w.T + memproj_b   (bf16)
    bgemm_kernel<true><<<dim3(D_ / 128, (B_ * H_) / 128, 1), 256, 65536>>>(
        z_bf, D_, 0, mpw_bf, D_, 0, y, D_, 0, mp_b, 0, B_ * H_, D_, D_);
    f2b_kernel<<<(B_ * H_ * D_ / 4 + 255) / 256, 256>>>(y, y_bf, B_ * H_ * D_);

    // 9) attn[b, h*256:e] = y_h[b] @ wv_h.T + bv_h   (bf16, batched heads)
    bgemm_kernel<true><<<dim3(DK_ / 128, 1, H_), 256, 65536>>>(
        y_bf, H_ * D_, D_, wv_bf, D_, (long long)DK_ * D_, attn, D_, DK_,
        bv, DK_, B_, DK_, D_);
    f2b_kernel<<<(B_ * D_ / 4 + 255) / 256, 256>>>(attn, attn_bf, B_ * D_);

    // 10) resp = attn @ wo.T + bo   (bf16)
    bgemm_kernel<true><<<dim3(D_ / 128, 1, 1), 256, 65536>>>(
        attn_bf, D_, 0, wo_bf, D_, 0, resp, D_, 0, bo, 0, B_, D_, D_);

    // 11) fin = [xf | resp]
    concat_kernel<<<(B_ * D_) / 256, 256>>>(xf, resp, fin);

    // 12) fus = gelu(fin @ fuse_w.T + fuse_b)   (fp32, split-K 8)
    gemm_kernel<64,128,16,4,8,true,0,8><<<dim3(16, 1, 8), 256>>>(
        fin, 2 * D_, 0, fuse_w, 2 * D_, 0, part, D_, (long long)B_ * D_,
        nullptr, 0, B_, D_, 2 * D_);
    reduce_kernel<1><<<dim3(B_ * D_ / 256, 1), 256>>>(
        part, fus, D_, 0, fuse_b, 0, B_ * D_, D_, 8);

    // 13) logits = fus @ head_w.T + head_b   (fp32, split-K 8)
    gemm_kernel<64,128,16,4,8,true,0,8><<<dim3(1, 1, 8), 256>>>(
        fus, D_, 0, head_w, D_, 0, part, C_, (long long)B_ * C_,
        nullptr, 0, B_, C_, D_);
    reduce_kernel<0><<<dim3((B_ * C_ + 255) / 256, 1), 256>>>(
        part, out, C_, 0, head_b, 0, B_ * C_, C_, 8);
}

// round 3
// speedup vs baseline: 4.5568x; 1.0134x over previous
#include <cuda_runtime.h>
#include <cuda_bf16.h>
#include <math.h>

#define B_  64
#define S_  196
#define D_  2048
#define H_  8
#define DK_ 256
#define M_  16384
#define KSEL 32
#define C_  29

// ---------------- scratch (static device globals; no allocation) -------------
__device__ float g_xm[B_ * D_];
__device__ float g_xf[B_ * D_];
__device__ float g_q [B_ * D_];
__device__ float g_t [B_ * H_ * D_];
__device__ float g_u [B_ * H_ * D_];
__device__ float g_sc[B_ * H_ * M_];               // 32 MB
__device__ float g_z [B_ * H_ * D_];
__device__ float g_y [B_ * H_ * D_];
__device__ float g_attn[B_ * D_];
__device__ float g_resp[B_ * D_];
__device__ float g_fin [B_ * 2 * D_];
__device__ float g_fus [B_ * D_];
__device__ float g_part[4 * 512 * 2048];           // 16 MB split-K partials

__device__ __nv_bfloat16 g_mem_bf[M_ * D_];        // 64 MB
__device__ __nv_bfloat16 g_mpw_bf[D_ * D_];
__device__ __nv_bfloat16 g_wv_bf [D_ * D_];
__device__ __nv_bfloat16 g_wo_bf [D_ * D_];
__device__ __nv_bfloat16 g_u_bf  [B_ * H_ * D_];
__device__ __nv_bfloat16 g_z_bf  [B_ * H_ * D_];
__device__ __nv_bfloat16 g_y_bf  [B_ * H_ * D_];
__device__ __nv_bfloat16 g_attn_bf[B_ * D_];

// ---------------- mean over S ------------------------------------------------
__global__ void mean_kernel(const float* __restrict__ x, float* __restrict__ xm) {
    int d = blockIdx.x * blockDim.x + threadIdx.x;
    int b = blockIdx.y;
    const float* xp = x + (size_t)b * S_ * D_ + d;
    float s = 0.f;
    #pragma unroll 4
    for (int i = 0; i < S_; ++i) s += xp[(size_t)i * D_];
    xm[b * D_ + d] = s * (1.0f / S_);
}

// ---------------- fp32 -> bf16 convert ---------------------------------------
__global__ void f2b_kernel(const float* __restrict__ a, __nv_bfloat16* __restrict__ o, int n) {
    int i = (blockIdx.x * blockDim.x + threadIdx.x) * 4;
    if (i < n) {
        float4 v = *(const float4*)(a + i);
        __nv_bfloat162 p0 = __floats2bfloat162_rn(v.x, v.y);
        __nv_bfloat162 p1 = __floats2bfloat162_rn(v.z, v.w);
        *(__nv_bfloat162*)(o + i)     = p0;
        *(__nv_bfloat162*)(o + i + 2) = p1;
    }
}

// ---------------- fp32 tiled SGEMM with optional split-K ----------------------
// C[M,N] = A[M,K] @ op(B) (+bias if SPLIT==1), op(B)=B[N,K]^T if TRANSB.
// blockIdx.z = batch * SPLIT + split. When SPLIT>1 caller points C at partials
// (ldc=N, sCz=M*N) and passes bias=nullptr; reduce_kernel finishes.
template<int BM, int BN, int BK, int TM, int TN, bool TRANSB, int EPI, int SPLIT>
__global__ void gemm_kernel(const float* __restrict__ A, int lda, long long sAz,
                            const float* __restrict__ B, int ldb, long long sBz,
                            float*       __restrict__ C, int ldc, long long sCz,
                            const float* __restrict__ bias, long long sbz,
                            int M, int N, int K)
{
    constexpr int THREADS = (BM / TM) * (BN / TN);
    __shared__ float As[BK][BM];
    __shared__ float Bs[BK][BN];

    const int zb = blockIdx.z / SPLIT;
    A += zb * sAz;
    B += zb * sBz;
    C += (size_t)blockIdx.z * sCz;
    const float* biasz = bias ? bias + zb * sbz : nullptr;
    const int Kc = K / SPLIT;
    const int koff = (blockIdx.z % SPLIT) * Kc;

    const int tid = threadIdx.x;
    const int m0 = blockIdx.y * BM;
    const int n0 = blockIdx.x * BN;
    const int tx = tid % (BN / TN);
    const int ty = tid / (BN / TN);

    float acc[TM][TN];
    #pragma unroll
    for (int i = 0; i < TM; ++i)
        #pragma unroll
        for (int j = 0; j < TN; ++j) acc[i][j] = 0.f;

    for (int k0 = koff; k0 < koff + Kc; k0 += BK) {
        #pragma unroll
        for (int i = tid; i < BM * BK; i += THREADS) {
            int m = i / BK, k = i % BK;
            int gm = m0 + m;
            As[k][m] = (gm < M) ? A[(size_t)gm * lda + k0 + k] : 0.f;
        }
        if (TRANSB) {
            #pragma unroll
            for (int i = tid; i < BN * BK; i += THREADS) {
                int n = i / BK, k = i % BK;
                int gn = n0 + n;
                Bs[k][n] = (gn < N) ? B[(size_t)gn * ldb + k0 + k] : 0.f;
            }
        } else {
            #pragma unroll
            for (int i = tid; i < BN * BK; i += THREADS) {
                int k = i / BN, n = i % BN;
                int gn = n0 + n;
                Bs[k][n] = (gn < N) ? B[(size_t)(k0 + k) * ldb + gn] : 0.f;
            }
        }
        __syncthreads();

        #pragma unroll
        for (int k = 0; k < BK; ++k) {
            float a[TM], b[TN];
            #pragma unroll
            for (int i = 0; i < TM; ++i) a[i] = As[k][ty * TM + i];
            #pragma unroll
            for (int j = 0; j < TN; ++j) b[j] = Bs[k][tx * TN + j];
            #pragma unroll
            for (int i = 0; i < TM; ++i)
                #pragma unroll
                for (int j = 0; j < TN; ++j) acc[i][j] += a[i] * b[j];
        }
        __syncthreads();
    }

    #pragma unroll
    for (int i = 0; i < TM; ++i) {
        int gm = m0 + ty * TM + i;
        if (gm >= M) continue;
        #pragma unroll
        for (int j = 0; j < TN; ++j) {
            int gn = n0 + tx * TN + j;
            if (gn >= N) continue;
            float v = acc[i][j];
            if (biasz) v += biasz[gn];
            if (EPI == 1) v = 0.5f * v * (1.0f + erff(v * 0.70710678118654752f));
            C[(size_t)gm * ldc + gn] = v;
        }
    }
}

// ---------------- split-K reduce ----------------------------------------------
template<int EPI>
__global__ void reduce_kernel(const float* __restrict__ part, float* __restrict__ C,
                              int ldc, long long sCz,
                              const float* __restrict__ bias, long long sbz,
                              int MN, int N, int SPLIT)
{
    int i = blockIdx.x * 256 + threadIdx.x;
    int z = blockIdx.y;
    if (i >= MN) return;
    const float* p = part + (size_t)z * SPLIT * MN + i;
    float s = 0.f;
    for (int k = 0; k < SPLIT; ++k) s += p[(size_t)k * MN];
    int n = i % N;
    if (bias) s += bias[z * sbz + n];
    if (EPI == 1) s = 0.5f * s * (1.0f + erff(s * 0.70710678118654752f));
    C[(size_t)z * sCz + (size_t)(i / N) * ldc + n] = s;
}

// ---------------- bf16 tensor-core TN GEMM ------------------------------------
// C[M,N](fp32) = A[M,K](bf16, K-major) @ B[N,K](bf16, K-major)^T (+bias)
// 128x128x64 tiles, 8 warps (4x2), cp.async double buffer, swizzled smem.
// Requires K%64==0, N%128==0; M guarded.
__device__ __forceinline__ unsigned bswz(int row, int chunk) {
    return (unsigned)(row * 64 + ((chunk ^ (row & 7)) * 8));   // bf16 elements
}

#define LDSM4(R, ADDR) asm volatile( \
    "ldmatrix.sync.aligned.m8n8.x4.shared.b16 {%0,%1,%2,%3}, [%4];" \
    : "=r"((R)[0]), "=r"((R)[1]), "=r"((R)[2]), "=r"((R)[3]) : "r"(ADDR))

#define MMA16816(D, A, B0, B1) asm volatile( \
    "mma.sync.aligned.m16n8k16.row.col.f32.bf16.bf16.f32 " \
    "{%0,%1,%2,%3},{%4,%5,%6,%7},{%8,%9},{%0,%1,%2,%3};" \
    : "+f"((D)[0]), "+f"((D)[1]), "+f"((D)[2]), "+f"((D)[3]) \
    : "r"((A)[0]), "r"((A)[1]), "r"((A)[2]), "r"((A)[3]), "r"(B0), "r"(B1))

template<bool HAS_BIAS>
__global__ __launch_bounds__(256) void bgemm_kernel(
    const __nv_bfloat16* __restrict__ A, int lda, long long sAz,
    const __nv_bfloat16* __restrict__ B, int ldb, long long sBz,
    float* __restrict__ C, int ldc, long long sCz,
    const float* __restrict__ bias, long long sbz,
    int M, int N, int K)
{
    extern __shared__ __nv_bfloat16 sm[];   // 2 stages * (A 8192 + B 8192) bf16
    const int tid  = threadIdx.x;
    const int lane = tid & 31;
    const int warp = tid >> 5;
    const int warpM = (warp >> 1) * 32;
    const int warpN = (warp & 1) * 64;
    const int m0 = blockIdx.y * 128;
    const int n0 = blockIdx.x * 128;
    const int z  = blockIdx.z;

    A += (size_t)z * sAz;
    B += (size_t)z * sBz;
    C += (size_t)z * sCz;

    unsigned sbase = (unsigned)__cvta_generic_to_shared(sm);

    float acc[2][8][4];
    #pragma unroll
    for (int a = 0; a < 2; ++a)
        #pragma unroll
        for (int b = 0; b < 8; ++b)
            #pragma unroll
            for (int c = 0; c < 4; ++c) acc[a][b][c] = 0.f;

    const int cidx = tid & 7;               // chunk column for loads
    const int rbase = tid >> 3;             // 0..31

    auto load_stage = [&](int s, int k0) {
        unsigned aB = sbase + (unsigned)s * 32768u;
        unsigned bB = aB + 16384u;
        #pragma unroll
        for (int j = 0; j < 4; ++j) {
            int r = j * 32 + rbase;
            const __nv_bfloat16* srcA = A + (size_t)(m0 + r) * lda + k0 + cidx * 8;
            unsigned dstA = aB + bswz(r, cidx) * 2u;
            int szA = (m0 + r < M) ? 16 : 0;
            asm volatile("cp.async.cg.shared.global [%0], [%1], 16, %2;\n"
                         :: "r"(dstA), "l"(srcA), "r"(szA));
            const __nv_bfloat16* srcB = B + (size_t)(n0 + r) * ldb + k0 + cidx * 8;
            unsigned dstB = bB + bswz(r, cidx) * 2u;
            asm volatile("cp.async.cg.shared.global [%0], [%1], 16, 16;\n"
                         :: "r"(dstB), "l"(srcB));
        }
    };

    auto compute = [&](int s) {
        unsigned aB = sbase + (unsigned)s * 32768u;
        unsigned bB = aB + 16384u;
        #pragma unroll
        for (int kk = 0; kk < 64; kk += 16) {
            unsigned af[2][4];
            #pragma unroll
            for (int mi = 0; mi < 2; ++mi) {
                int row = warpM + mi * 16 + (lane & 15);
                int ch  = (kk >> 3) + (lane >> 4);
                unsigned addr = aB + bswz(row, ch) * 2u;
                LDSM4(af[mi], addr);
            }
            unsigned bf[4][4];
            #pragma unroll
            for (int ni = 0; ni < 4; ++ni) {
                int g = lane >> 3;
                int row = warpN + ni * 16 + ((g >> 1) << 3) + (lane & 7);
                int ch  = (kk >> 3) + (g & 1);
                unsigned addr = bB + bswz(row, ch) * 2u;
                LDSM4(bf[ni], addr);
            }
            #pragma unroll
            for (int mi = 0; mi < 2; ++mi)
                #pragma unroll
                for (int n8 = 0; n8 < 8; ++n8) {
                    unsigned* bb = &bf[n8 >> 1][(n8 & 1) * 2];
                    MMA16816(acc[mi][n8], af[mi], bb[0], bb[1]);
                }
        }
    };

    const int KT = K >> 6;
    load_stage(0, 0);
    asm volatile("cp.async.commit_group;\n" ::);
    for (int t = 0; t < KT; ++t) {
        if (t + 1 < KT) {
            load_stage((t + 1) & 1, (t + 1) << 6);
            asm volatile("cp.async.commit_group;\n" ::);
            asm volatile("cp.async.wait_group 1;\n" ::);
        } else {
            asm volatile("cp.async.wait_group 0;\n" ::);
        }
        __syncthreads();
        compute(t & 1);
        __syncthreads();
    }

    // epilogue
    #pragma unroll
    for (int mi = 0; mi < 2; ++mi) {
        int row = m0 + warpM + mi * 16 + (lane >> 2);
        #pragma unroll
        for (int n8 = 0; n8 < 8; ++n8) {
            int col = n0 + warpN + n8 * 8 + (lane & 3) * 2;
            float b0 = 0.f, b1 = 0.f;
            if (HAS_BIAS) {
                b0 = bias[z * sbz + col];
                b1 = bias[z * sbz + col + 1];
            }
            if (row < M) {
                float2 v = make_float2(acc[mi][n8][0] + b0, acc[mi][n8][1] + b1);
                *(float2*)(C + (size_t)row * ldc + col) = v;
            }
            if (row + 8 < M) {
                float2 v = make_float2(acc[mi][n8][2] + b0, acc[mi][n8][3] + b1);
                *(float2*)(C + (size_t)(row + 8) * ldc + col) = v;
            }
        }
    }
}

// ---------------- top-64 coarse -> exact fp32 rescore -> top-32 + z ----------
__global__ __launch_bounds__(256) void topk_kernel(
    const float* __restrict__ scores, const float* __restrict__ u,
    const float* __restrict__ mem, float* __restrict__ z,
    __nv_bfloat16* __restrict__ zbf)
{
    extern __shared__ float dyn[];
    float* sv = dyn;            // M_
    float* us = dyn + M_;       // D_
    __shared__ float warpv[8];
    __shared__ int   warpi[8];
    __shared__ int   s_wini;
    __shared__ int   cand[64];
    __shared__ float scE[64];
    __shared__ float pw[KSEL];
    __shared__ int   pidx[KSEL];

    const int row = blockIdx.x;
    const int tid = threadIdx.x;
    const int lane = tid & 31;
    const int warp = tid >> 5;
    const float* sr = scores + (size_t)row * M_;
    const float* ur = u + (size_t)row * D_;

    // load row into smem; per-thread cached argmax over strided slice
    float bv = -INFINITY; int bi = 0;
    #pragma unroll 4
    for (int j = 0; j < M_ / 256; ++j) {
        int i = tid + j * 256;
        float v = sr[i];
        sv[i] = v;
        if (v > bv) { bv = v; bi = i; }
    }
    for (int j = tid; j < D_; j += 256) us[j] = ur[j];
    __syncthreads();

    // coarse top-64 (value desc, lower index wins ties)
    for (int sel = 0; sel < 64; ++sel) {
        float v = bv; int ix = bi;
        #pragma unroll
        for (int o = 16; o > 0; o >>= 1) {
            float v2 = __shfl_down_sync(0xffffffffu, v, o);
            int   i2 = __shfl_down_sync(0xffffffffu, ix, o);
            if (v2 > v || (v2 == v && i2 < ix)) { v = v2; ix = i2; }
        }
        if (lane == 0) { warpv[warp] = v; warpi[warp] = ix; }
        __syncthreads();
        if (warp == 0) {
            float v3 = (lane < 8) ? warpv[lane] : -INFINITY;
            int   i3 = (lane < 8) ? warpi[lane] : 0x7fffffff;
            #pragma unroll
            for (int o = 4; o > 0; o >>= 1) {
                float v2 = __shfl_down_sync(0xffffffffu, v3, o);
                int   i2 = __shfl_down_sync(0xffffffffu, i3, o);
                if (v2 > v3 || (v2 == v3 && i2 < i3)) { v3 = v2; i3 = i2; }
            }
            if (lane == 0) { s_wini = i3; cand[sel] = i3; }
        }
        __syncthreads();
        int w = s_wini;
        if ((w & 255) == tid) {
            sv[w] = -INFINITY;
            bv = -INFINITY; bi = 0;
            #pragma unroll 4
            for (int j = 0; j < M_ / 256; ++j) {
                int i = tid + j * 256;
                float vv = sv[i];
                if (vv > bv) { bv = vv; bi = i; }
            }
        }
        __syncthreads();
    }

    // exact fp32 rescore of 64 candidates
    for (int r8 = 0; r8 < 8; ++r8) {
        int c = r8 * 8 + warp;
        const float* mr = mem + (size_t)cand[c] * D_;
        float s = 0.f;
        #pragma unroll 8
        for (int j = lane; j < D_; j += 32) s += us[j] * mr[j];
        #pragma unroll
        for (int o = 16; o > 0; o >>= 1) s += __shfl_down_sync(0xffffffffu, s, o);
        if (lane == 0) scE[c] = s;
    }
    __syncthreads();

    // exact top-32 of the 64 (warp 0), then softmax(sel/16)
    if (warp == 0) {
        float v0 = scE[lane],      v1 = scE[32 + lane];
        int   i0 = cand[lane],     i1 = cand[32 + lane];
        for (int s = 0; s < KSEL; ++s) {
            float v; int ix, slot;
            if (v0 > v1 || (v0 == v1 && i0 < i1)) { v = v0; ix = i0; slot = lane; }
            else                                  { v = v1; ix = i1; slot = 32 + lane; }
            #pragma unroll
            for (int o = 16; o > 0; o >>= 1) {
                float v2 = __shfl_down_sync(0xffffffffu, v, o);
                int   x2 = __shfl_down_sync(0xffffffffu, ix, o);
                int   s2 = __shfl_down_sync(0xffffffffu, slot, o);
                if (v2 > v || (v2 == v && x2 < ix)) { v = v2; ix = x2; slot = s2; }
            }
            v    = __shfl_sync(0xffffffffu, v, 0);
            ix   = __shfl_sync(0xffffffffu, ix, 0);
            slot = __shfl_sync(0xffffffffu, slot, 0);
            if (slot == lane)      v0 = -INFINITY;
            if (slot == 32 + lane) v1 = -INFINITY;
            if (lane == 0) { pw[s] = v; pidx[s] = ix; }
        }
        if (lane == 0) {
            float mx = pw[0], ssum = 0.f;
            for (int k = 0; k < KSEL; ++k) {
                float e = expf((pw[k] - mx) * 0.0625f);
                pw[k] = e; ssum += e;
            }
            float inv = 1.f / ssum;
            for (int k = 0; k < KSEL; ++k) pw[k] *= inv;
        }
    }
    __syncthreads();

    // z = sum_k p_k * mem[idx_k]
    for (int d = tid; d < D_; d += 256) {
        float acc = 0.f;
        #pragma unroll
        for (int k = 0; k < KSEL; ++k) acc += pw[k] * mem[(size_t)pidx[k] * D_ + d];
        z[(size_t)row * D_ + d] = acc;
        zbf[(size_t)row * D_ + d] = __float2bfloat16(acc);
    }
}

// ---------------- concat [xf | resp] ------------------------------------------
__global__ void concat_kernel(const float* __restrict__ xf,
                              const float* __restrict__ resp,
                              float* __restrict__ fin)
{
    int i = blockIdx.x * blockDim.x + threadIdx.x;
    int b = i / D_, d = i % D_;
    fin[(size_t)b * 2 * D_ + d]      = xf[i];
    fin[(size_t)b * 2 * D_ + D_ + d] = resp[i];
}

// ---------------- launch -------------------------------------------------------
extern "C" void kernel_launch(void* const* d_in, const int* in_sizes, int n_in,
                              void* d_out, int out_size)
{
    const float* x      = (const float*)d_in[0];
    const float* mem    = (const float*)d_in[2];
    const float* ff_w   = (const float*)d_in[3];
    const float* ff_b   = (const float*)d_in[4];
    const float* mp_w   = (const float*)d_in[5];
    const float* mp_b   = (const float*)d_in[6];
    const float* wq     = (const float*)d_in[7];
    const float* bq     = (const float*)d_in[8];
    const float* wk     = (const float*)d_in[9];
    const float* wv     = (const float*)d_in[11];
    const float* bv     = (const float*)d_in[12];
    const float* wo     = (const float*)d_in[13];
    const float* bo     = (const float*)d_in[14];
    const float* fuse_w = (const float*)d_in[15];
    const float* fuse_b = (const float*)d_in[16];
    const float* head_w = (const float*)d_in[17];
    const float* head_b = (const float*)d_in[18];
    float* out = (float*)d_out;

    float *xm, *xf, *q, *t, *u, *sc, *z, *y, *attn, *resp, *fin, *fus, *part;
    __nv_bfloat16 *mem_bf, *mpw_bf, *wv_bf, *wo_bf, *u_bf, *z_bf, *y_bf, *attn_bf;
    cudaGetSymbolAddress((void**)&xm,   g_xm);
    cudaGetSymbolAddress((void**)&xf,   g_xf);
    cudaGetSymbolAddress((void**)&q,    g_q);
    cudaGetSymbolAddress((void**)&t,    g_t);
    cudaGetSymbolAddress((void**)&u,    g_u);
    cudaGetSymbolAddress((void**)&sc,   g_sc);
    cudaGetSymbolAddress((void**)&z,    g_z);
    cudaGetSymbolAddress((void**)&y,    g_y);
    cudaGetSymbolAddress((void**)&attn, g_attn);
    cudaGetSymbolAddress((void**)&resp, g_resp);
    cudaGetSymbolAddress((void**)&fin,  g_fin);
    cudaGetSymbolAddress((void**)&fus,  g_fus);
    cudaGetSymbolAddress((void**)&part, g_part);
    cudaGetSymbolAddress((void**)&mem_bf,  g_mem_bf);
    cudaGetSymbolAddress((void**)&mpw_bf,  g_mpw_bf);
    cudaGetSymbolAddress((void**)&wv_bf,   g_wv_bf);
    cudaGetSymbolAddress((void**)&wo_bf,   g_wo_bf);
    cudaGetSymbolAddress((void**)&u_bf,    g_u_bf);
    cudaGetSymbolAddress((void**)&z_bf,    g_z_bf);
    cudaGetSymbolAddress((void**)&y_bf,    g_y_bf);
    cudaGetSymbolAddress((void**)&attn_bf, g_attn_bf);

    cudaFuncSetAttribute(bgemm_kernel<false>,
                         cudaFuncAttributeMaxDynamicSharedMemorySize, 65536);
    cudaFuncSetAttribute(bgemm_kernel<true>,
                         cudaFuncAttributeMaxDynamicSharedMemorySize, 65536);
    cudaFuncSetAttribute(topk_kernel,
                         cudaFuncAttributeMaxDynamicSharedMemorySize, (M_ + D_) * 4);

    // weight conversions (deterministic; replayed each graph launch)
    f2b_kernel<<<(M_ * D_ / 4 + 255) / 256, 256>>>(mem, mem_bf, M_ * D_);
    f2b_kernel<<<(D_ * D_ / 4 + 255) / 256, 256>>>(mp_w, mpw_bf, D_ * D_);
    f2b_kernel<<<(D_ * D_ / 4 + 255) / 256, 256>>>(wv, wv_bf, D_ * D_);
    f2b_kernel<<<(D_ * D_ / 4 + 255) / 256, 256>>>(wo, wo_bf, D_ * D_);

    // 1) xm = mean_s(x)
    mean_kernel<<<dim3(D_ / 256, B_), 256>>>(x, xm);

    // 2) xf = xm @ ff_w.T + ff_b   (fp32, split-K 8)
    gemm_kernel<64,128,16,4,8,true,0,8><<<dim3(16, 1, 8), 256>>>(
        xm, D_, 0, ff_w, D_, 0, part, D_, (long long)B_ * D_, nullptr, 0, B_, D_, D_);
    reduce_kernel<0><<<dim3(B_ * D_ / 256, 1), 256>>>(
        part, xf, D_, 0, ff_b, 0, B_ * D_, D_, 8);

    // 3) q = xf @ wq.T + bq        (fp32, split-K 8)
    gemm_kernel<64,128,16,4,8,true,0,8><<<dim3(16, 1, 8), 256>>>(
        xf, D_, 0, wq, D_, 0, part, D_, (long long)B_ * D_, nullptr, 0, B_, D_, D_);
    reduce_kernel<0><<<dim3(B_ * D_ / 256, 1), 256>>>(
        part, q, D_, 0, bq, 0, B_ * D_, D_, 8);

    // 4) t[b*8+h] = q_h[b] @ wk_h  (fp32, batched over heads)
    gemm_kernel<64,128,16,4,8,false,0,1><<<dim3(16, 1, H_), 256>>>(
        q, D_, DK_, wk, D_, (long long)DK_ * D_, t, H_ * D_, D_,
        nullptr, 0, B_, D_, DK_);

    // 5) u = t @ memproj_w         (fp32, split-K 4)
    gemm_kernel<128,128,8,8,8,false,0,4><<<dim3(16, 4, 4), 256>>>(
        t, D_, 0, mp_w, D_, 0, part, D_, (long long)B_ * H_ * D_,
        nullptr, 0, B_ * H_, D_, D_);
    reduce_kernel<0><<<dim3(B_ * H_ * D_ / 256, 1), 256>>>(
        part, u, D_, 0, nullptr, 0, B_ * H_ * D_, D_, 4);

    f2b_kernel<<<(B_ * H_ * D_ / 4 + 255) / 256, 256>>>(u, u_bf, B_ * H_ * D_);

    // 6) scores = u @ mem.T        (bf16 tensor cores, fp32 accum)
    bgemm_kernel<false><<<dim3(M_ / 128, (B_ * H_) / 128, 1), 256, 65536>>>(
        u_bf, D_, 0, mem_bf, D_, 0, sc, M_, 0, nullptr, 0, B_ * H_, M_, D_);

    // 7) coarse top-64 -> exact rescore -> top-32 -> softmax -> z
    topk_kernel<<<B_ * H_, 256, (M_ + D_) * 4>>>(sc, u, mem, z, z_bf);

    // 8) y = z @ memproj_w.T + memproj_b   (bf16)
    bgemm_kernel<true><<<dim3(D_ / 128, (B_ * H_) / 128, 1), 256, 65536>>>(
        z_bf, D_, 0, mpw_bf, D_, 0, y, D_, 0, mp_b, 0, B_ * H_, D_, D_);
    f2b_kernel<<<(B_ * H_ * D_ / 4 + 255) / 256, 256>>>(y, y_bf, B_ * H_ * D_);

    // 9) attn[b, h*256:e] = y_h[b] @ wv_h.T + bv_h   (bf16, batched heads)
    bgemm_kernel<true><<<dim3(DK_ / 128, 1, H_), 256, 65536>>>(
        y_bf, H_ * D_, D_, wv_bf, D_, (long long)DK_ * D_, attn, D_, DK_,
        bv, DK_, B_, DK_, D_);
    f2b_kernel<<<(B_ * D_ / 4 + 255) / 256, 256>>>(attn, attn_bf, B_ * D_);

    // 10) resp = attn @ wo.T + bo   (bf16)
    bgemm_kernel<true><<<dim3(D_ / 128, 1, 1), 256, 65536>>>(
        attn_bf, D_, 0, wo_bf, D_, 0, resp, D_, 0, bo, 0, B_, D_, D_);

    // 11) fin = [xf | resp]
    concat_kernel<<<(B_ * D_) / 256, 256>>>(xf, resp, fin);

    // 12) fus = gelu(fin @ fuse_w.T + fuse_b)   (fp32, split-K 8)
    gemm_kernel<64,128,16,4,8,true,0,8><<<dim3(16, 1, 8), 256>>>(
        fin, 2 * D_, 0, fuse_w, 2 * D_, 0, part, D_, (long long)B_ * D_,
        nullptr, 0, B_, D_, 2 * D_);
    reduce_kernel<1><<<dim3(B_ * D_ / 256, 1), 256>>>(
        part, fus, D_, 0, fuse_b, 0, B_ * D_, D_, 8);

    // 13) logits = fus @ head_w.T + head_b   (fp32, split-K 8)
    gemm_kernel<64,128,16,4,8,true,0,8><<<dim3(1, 1, 8), 256>>>(
        fus, D_, 0, head_w, D_, 0, part, C_, (long long)B_ * C_,
        nullptr, 0, B_, C_, D_);
    reduce_kernel<0><<<dim3((B_ * C_ + 255) / 256, 1), 256>>>(
        part, out, C_, 0, head_b, 0, B_ * C_, C_, 8);
}

// round 4
// speedup vs baseline: 8.2306x; 1.8062x over previous
#include <cuda_runtime.h>
#include <cuda_bf16.h>
#include <math.h>

#define B_  64
#define S_  196
#define D_  2048
#define H_  8
#define DK_ 256
#define M_  16384
#define KSEL 32
#define C_  29

__device__ float g_xm [B_ * D_];
__device__ float g_q  [B_ * D_];
__device__ float g_t  [B_ * H_ * D_];
__device__ float g_u  [B_ * H_ * D_];
__device__ float g_sc [B_ * H_ * M_];
__device__ float g_z  [B_ * H_ * D_];
__device__ float g_y  [B_ * H_ * D_];
__device__ float g_attn[B_ * D_];
__device__ float g_fin[B_ * 2 * D_];
__device__ float g_fus[B_ * D_];
__device__ float g_part[4 * 512 * 2048];
__device__ float g_wkT [D_ * D_];
__device__ float g_mpwT[D_ * D_];
__device__ __nv_bfloat16 g_u_bf [B_ * H_ * D_];
__device__ __nv_bfloat16 g_mem_bf[M_ * D_];

__device__ __forceinline__ float gelu_exact(float v) {
    return 0.5f * v * (1.0f + erff(v * 0.70710678118654752f));
}
__device__ __forceinline__ void split2(float a, float b, unsigned& hi, unsigned& lo) {
    __nv_bfloat162 h = __floats2bfloat162_rn(a, b);
    __nv_bfloat162 l = __floats2bfloat162_rn(a - __bfloat162float(h.x),
                                             b - __bfloat162float(h.y));
    hi = *(unsigned*)&h; lo = *(unsigned*)&l;
}

#define LDSM4(R, ADDR) asm volatile( \
    "ldmatrix.sync.aligned.m8n8.x4.shared.b16 {%0,%1,%2,%3}, [%4];" \
    : "=r"((R)[0]), "=r"((R)[1]), "=r"((R)[2]), "=r"((R)[3]) : "r"(ADDR))
#define MMA16816(D, A, B0, B1) asm volatile( \
    "mma.sync.aligned.m16n8k16.row.col.f32.bf16.bf16.f32 " \
    "{%0,%1,%2,%3},{%4,%5,%6,%7},{%8,%9},{%0,%1,%2,%3};" \
    : "+f"((D)[0]), "+f"((D)[1]), "+f"((D)[2]), "+f"((D)[3]) \
    : "r"((A)[0]), "r"((A)[1]), "r"((A)[2]), "r"((A)[3]), "r"(B0), "r"(B1))

// ---------------- transpose fp32 DxD ----------------
__global__ void transpose_kernel(const float* __restrict__ in, float* __restrict__ out) {
    __shared__ float tile[32][33];
    int x = blockIdx.x * 32 + threadIdx.x;
    #pragma unroll
    for (int j = threadIdx.y; j < 32; j += 8)
        tile[j][threadIdx.x] = in[(size_t)(blockIdx.y * 32 + j) * D_ + x];
    __syncthreads();
    int xo = blockIdx.y * 32 + threadIdx.x;
    #pragma unroll
    for (int j = threadIdx.y; j < 32; j += 8)
        out[(size_t)(blockIdx.x * 32 + j) * D_ + xo] = tile[threadIdx.x][j];
}

// ---------------- fp32 -> bf16 grid-stride ----------------
__global__ void f2b_kernel(const float* __restrict__ a, __nv_bfloat16* __restrict__ o, int n) {
    int stride = gridDim.x * blockDim.x * 8;
    for (int i = (blockIdx.x * blockDim.x + threadIdx.x) * 8; i < n; i += stride) {
        float4 v0 = *(const float4*)(a + i);
        float4 v1 = *(const float4*)(a + i + 4);
        __nv_bfloat162 r[4];
        r[0] = __floats2bfloat162_rn(v0.x, v0.y);
        r[1] = __floats2bfloat162_rn(v0.z, v0.w);
        r[2] = __floats2bfloat162_rn(v1.x, v1.y);
        r[3] = __floats2bfloat162_rn(v1.z, v1.w);
        *(uint4*)(o + i) = *(uint4*)r;
    }
}

// ---------------- mean over S ----------------
__global__ void mean_kernel(const float* __restrict__ x, float* __restrict__ xm) {
    int d4 = blockIdx.x * blockDim.x + threadIdx.x;    // 0..511
    int b = blockIdx.y;
    const float4* xp = (const float4*)(x + (size_t)b * S_ * D_) + d4;
    float4 s = make_float4(0.f, 0.f, 0.f, 0.f);
    #pragma unroll 4
    for (int i = 0; i < S_; ++i) {
        float4 v = xp[(size_t)i * (D_ / 4)];
        s.x += v.x; s.y += v.y; s.z += v.z; s.w += v.w;
    }
    const float inv = 1.0f / S_;
    ((float4*)(xm + (size_t)b * D_))[d4] =
        make_float4(s.x * inv, s.y * inv, s.z * inv, s.w * inv);
}

// ---------------- unified TC TN GEMM, fp32 in/out, in-reg bf16 (hi/lo) --------
// C[M,N] = A[M,K] @ B[N,K]^T. NSPLIT 3 = hi/lo split; 1 = plain bf16.
// blockIdx.z = zb*SPLITK + sk. 128x128x32 tiles, 256 thr. SW64 swizzle.
template<int NSPLIT, int SPLITK>
__global__ __launch_bounds__(256) void bgemm3_kernel(
    const float* __restrict__ A, int lda, long long sAz,
    const float* __restrict__ Bm, int ldb, long long sBz,
    float* __restrict__ C, int ldc, long long sCz,
    const float* __restrict__ bias, int sbz,
    int M, int N, int K)
{
    extern __shared__ __nv_bfloat16 sm[];
    constexpr int STAGE = (NSPLIT == 3) ? 16384 : 8192;
    const int tid = threadIdx.x, lane = tid & 31, warp = tid >> 5;
    const int warpM = (warp >> 1) * 32, warpN = (warp & 1) * 64;
    const int m0 = blockIdx.y * 128, n0 = blockIdx.x * 128;
    const int zb = blockIdx.z / SPLITK, sk = blockIdx.z % SPLITK;
    const int Kc = K / SPLITK, k0base = sk * Kc;

    A  += (size_t)zb * sAz;
    Bm += (size_t)zb * sBz;
    C  += (size_t)blockIdx.z * sCz;

    const int cc = tid & 7, rr = tid >> 3;
    float4 ra[4], rb[4];
    unsigned sbase = (unsigned)__cvta_generic_to_shared(sm);

    float acc[2][8][4];
    #pragma unroll
    for (int a = 0; a < 2; ++a)
        #pragma unroll
        for (int b = 0; b < 8; ++b)
            #pragma unroll
            for (int c = 0; c < 4; ++c) acc[a][b][c] = 0.f;

    auto ldg = [&](int kt) {
        int kcol = k0base + kt * 32 + cc * 4;
        #pragma unroll
        for (int j = 0; j < 4; ++j) {
            int rA = m0 + j * 32 + rr;
            ra[j] = (rA < M) ? *(const float4*)(A + (size_t)rA * lda + kcol)
                             : make_float4(0.f, 0.f, 0.f, 0.f);
            int rB = n0 + j * 32 + rr;
            rb[j] = (rB < N) ? *(const float4*)(Bm + (size_t)rB * ldb + kcol)
                             : make_float4(0.f, 0.f, 0.f, 0.f);
        }
    };
    auto sts = [&](int s) {
        __nv_bfloat16* base = sm + s * STAGE;
        #pragma unroll
        for (int j = 0; j < 4; ++j) {
            int row = j * 32 + rr;
            int off = row * 32 + ((((cc >> 1) ^ ((row >> 1) & 3)) << 3)) + ((cc & 1) << 2);
            unsigned h0, h1, l0, l1;
            split2(ra[j].x, ra[j].y, h0, l0);
            split2(ra[j].z, ra[j].w, h1, l1);
            *(uint2*)(base + off) = make_uint2(h0, h1);
            if (NSPLIT == 3) *(uint2*)(base + 8192 + off) = make_uint2(l0, l1);
            split2(rb[j].x, rb[j].y, h0, l0);
            split2(rb[j].z, rb[j].w, h1, l1);
            *(uint2*)(base + 4096 + off) = make_uint2(h0, h1);
            if (NSPLIT == 3) *(uint2*)(base + 12288 + off) = make_uint2(l0, l1);
        }
    };
    auto compute = [&](int s) {
        unsigned aB = sbase + (unsigned)(s * STAGE) * 2u;
        unsigned bB = aB + 8192u;
        #pragma unroll
        for (int kk = 0; kk < 32; kk += 16) {
            unsigned ah[2][4], al[2][4];
            #pragma unroll
            for (int mi = 0; mi < 2; ++mi) {
                int row = warpM + mi * 16 + (lane & 15);
                int ch = (kk >> 3) + (lane >> 4);
                unsigned addr = aB +
                    (unsigned)(row * 32 + ((ch ^ ((row >> 1) & 3)) << 3)) * 2u;
                LDSM4(ah[mi], addr);
                if (NSPLIT == 3) LDSM4(al[mi], addr + 16384u);
            }
            unsigned bh[4][4], bl[4][4];
            #pragma unroll
            for (int ni = 0; ni < 4; ++ni) {
                int g = lane >> 3;
                int row = warpN + ni * 16 + ((g >> 1) << 3) + (lane & 7);
                int ch = (kk >> 3) + (g & 1);
                unsigned addr = bB +
                    (unsigned)(row * 32 + ((ch ^ ((row >> 1) & 3)) << 3)) * 2u;
                LDSM4(bh[ni], addr);
                if (NSPLIT == 3) LDSM4(bl[ni], addr + 16384u);
            }
            #pragma unroll
            for (int mi = 0; mi < 2; ++mi)
                #pragma unroll
                for (int n8 = 0; n8 < 8; ++n8) {
                    unsigned* hb = &bh[n8 >> 1][(n8 & 1) * 2];
                    MMA16816(acc[mi][n8], ah[mi], hb[0], hb[1]);
                    if (NSPLIT == 3) {
                        unsigned* lb = &bl[n8 >> 1][(n8 & 1) * 2];
                        MMA16816(acc[mi][n8], ah[mi], lb[0], lb[1]);
                        MMA16816(acc[mi][n8], al[mi], hb[0], hb[1]);
                    }
                }
        }
    };

    const int KT = Kc / 32;
    ldg(0);
    sts(0);
    __syncthreads();
    for (int t = 0; t < KT; ++t) {
        if (t + 1 < KT) ldg(t + 1);
        compute(t & 1);
        __syncthreads();
        if (t + 1 < KT) { sts((t + 1) & 1); __syncthreads(); }
    }

    #pragma unroll
    for (int mi = 0; mi < 2; ++mi) {
        int row = m0 + warpM + mi * 16 + (lane >> 2);
        #pragma unroll
        for (int n8 = 0; n8 < 8; ++n8) {
            int col = n0 + warpN + n8 * 8 + (lane & 3) * 2;
            float b0 = 0.f, b1 = 0.f;
            if (bias) { b0 = bias[zb * sbz + col]; b1 = bias[zb * sbz + col + 1]; }
            if (row < M)
                *(float2*)(C + (size_t)row * ldc + col) =
                    make_float2(acc[mi][n8][0] + b0, acc[mi][n8][1] + b1);
            if (row + 8 < M)
                *(float2*)(C + (size_t)(row + 8) * ldc + col) =
                    make_float2(acc[mi][n8][2] + b0, acc[mi][n8][3] + b1);
        }
    }
}

// ---------------- split-K reduce (+bias, +gelu, +bf16 mirror) ----------------
template<int EPI, bool WBF>
__global__ void reduce_kernel(const float* __restrict__ part, float* __restrict__ C,
                              int ldc, int cZ, const float* __restrict__ bias, int sbz,
                              __nv_bfloat16* __restrict__ Cbf,
                              int MN, int N, int SPLIT)
{
    int i = blockIdx.x * 256 + threadIdx.x;
    int z = blockIdx.y;
    if (i >= MN) return;
    const float* p = part + (size_t)z * SPLIT * MN + i;
    float s = 0.f;
    for (int k = 0; k < SPLIT; ++k) s += p[(size_t)k * MN];
    int n = i % N;
    if (bias) s += bias[z * sbz + n];
    if (EPI == 1) s = gelu_exact(s);
    C[(size_t)z * cZ + (size_t)(i / N) * ldc + n] = s;
    if (WBF) Cbf[(size_t)z * MN + i] = __float2bfloat16(s);
}

// ---------------- scores: bf16 TC TN GEMM, 3-stage cp.async -------------------
__device__ __forceinline__ unsigned bswz(int row, int chunk) {
    return (unsigned)(row * 64 + ((chunk ^ (row & 7)) * 8));
}
__global__ __launch_bounds__(256) void bgemm_kernel(
    const __nv_bfloat16* __restrict__ A, int lda,
    const __nv_bfloat16* __restrict__ B, int ldb,
    float* __restrict__ C, int ldc, int M, int N, int K)
{
    extern __shared__ __nv_bfloat16 sm[];
    const int tid = threadIdx.x, lane = tid & 31, warp = tid >> 5;
    const int warpM = (warp >> 1) * 32, warpN = (warp & 1) * 64;
    const int m0 = blockIdx.y * 128, n0 = blockIdx.x * 128;
    unsigned sbase = (unsigned)__cvta_generic_to_shared(sm);

    float acc[2][8][4];
    #pragma unroll
    for (int a = 0; a < 2; ++a)
        #pragma unroll
        for (int b = 0; b < 8; ++b)
            #pragma unroll
            for (int c = 0; c < 4; ++c) acc[a][b][c] = 0.f;

    const int cidx = tid & 7, rbase = tid >> 3;
    auto load_stage = [&](int s, int k0) {
        unsigned aB = sbase + (unsigned)s * 32768u;
        unsigned bB = aB + 16384u;
        #pragma unroll
        for (int j = 0; j < 4; ++j) {
            int r = j * 32 + rbase;
            const __nv_bfloat16* srcA = A + (size_t)(m0 + r) * lda + k0 + cidx * 8;
            int szA = (m0 + r < M) ? 16 : 0;
            asm volatile("cp.async.cg.shared.global [%0], [%1], 16, %2;\n"
                         :: "r"(aB + bswz(r, cidx) * 2u), "l"(srcA), "r"(szA));
            const __nv_bfloat16* srcB = B + (size_t)(n0 + r) * ldb + k0 + cidx * 8;
            asm volatile("cp.async.cg.shared.global [%0], [%1], 16, 16;\n"
                         :: "r"(bB + bswz(r, cidx) * 2u), "l"(srcB));
        }
        asm volatile("cp.async.commit_group;\n" ::);
    };
    auto compute = [&](int s) {
        unsigned aB = sbase + (unsigned)s * 32768u;
        unsigned bB = aB + 16384u;
        #pragma unroll
        for (int kk = 0; kk < 64; kk += 16) {
            unsigned af[2][4];
            #pragma unroll
            for (int mi = 0; mi < 2; ++mi) {
                int row = warpM + mi * 16 + (lane & 15);
                int ch = (kk >> 3) + (lane >> 4);
                LDSM4(af[mi], aB + bswz(row, ch) * 2u);
            }
            unsigned bf[4][4];
            #pragma unroll
            for (int ni = 0; ni < 4; ++ni) {
                int g = lane >> 3;
                int row = warpN + ni * 16 + ((g >> 1) << 3) + (lane & 7);
                int ch = (kk >> 3) + (g & 1);
                LDSM4(bf[ni], bB + bswz(row, ch) * 2u);
            }
            #pragma unroll
            for (int mi = 0; mi < 2; ++mi)
                #pragma unroll
                for (int n8 = 0; n8 < 8; ++n8) {
                    unsigned* bb = &bf[n8 >> 1][(n8 & 1) * 2];
                    MMA16816(acc[mi][n8], af[mi], bb[0], bb[1]);
                }
        }
    };

    const int KT = K >> 6;
    load_stage(0, 0);
    load_stage(1, 64);
    for (int t = 0; t < KT; ++t) {
        if (t + 2 < KT) {
            load_stage((t + 2) % 3, (t + 2) << 6);
            asm volatile("cp.async.wait_group 2;\n" ::);
        } else {
            asm volatile("cp.async.wait_group 0;\n" ::);
        }
        __syncthreads();
        compute(t % 3);
        __syncthreads();
    }

    #pragma unroll
    for (int mi = 0; mi < 2; ++mi) {
        int row = m0 + warpM + mi * 16 + (lane >> 2);
        #pragma unroll
        for (int n8 = 0; n8 < 8; ++n8) {
            int col = n0 + warpN + n8 * 8 + (lane & 3) * 2;
            if (row < M)
                *(float2*)(C + (size_t)row * ldc + col) =
                    make_float2(acc[mi][n8][0], acc[mi][n8][1]);
            if (row + 8 < M)
                *(float2*)(C + (size_t)(row + 8) * ldc + col) =
                    make_float2(acc[mi][n8][2], acc[mi][n8][3]);
        }
    }
}

// ---------------- top-64 coarse -> exact fp32 rescore -> top-32 + z ----------
__global__ __launch_bounds__(256) void topk_kernel(
    const float* __restrict__ scores, const float* __restrict__ u,
    const float* __restrict__ mem, float* __restrict__ z)
{
    extern __shared__ float dyn[];
    float* sv = dyn;
    float* us = dyn + M_;
    __shared__ float warpv[8];
    __shared__ int   warpi[8];
    __shared__ int   s_wini;
    __shared__ int   cand[64];
    __shared__ float scE[64];
    __shared__ float pw[KSEL];
    __shared__ int   pidx[KSEL];

    const int row = blockIdx.x, tid = threadIdx.x;
    const int lane = tid & 31, warp = tid >> 5;
    const float* sr = scores + (size_t)row * M_;
    const float* ur = u + (size_t)row * D_;

    float bv = -INFINITY; int bi = 0;
    #pragma unroll 4
    for (int j = 0; j < M_ / 256; ++j) {
        int i = tid + j * 256;
        float v = sr[i];
        sv[i] = v;
        if (v > bv) { bv = v; bi = i; }
    }
    for (int j = tid; j < D_; j += 256) us[j] = ur[j];
    __syncthreads();

    for (int sel = 0; sel < 64; ++sel) {
        float v = bv; int ix = bi;
        #pragma unroll
        for (int o = 16; o > 0; o >>= 1) {
            float v2 = __shfl_down_sync(0xffffffffu, v, o);
            int   i2 = __shfl_down_sync(0xffffffffu, ix, o);
            if (v2 > v || (v2 == v && i2 < ix)) { v = v2; ix = i2; }
        }
        if (lane == 0) { warpv[warp] = v; warpi[warp] = ix; }
        __syncthreads();
        if (warp == 0) {
            float v3 = (lane < 8) ? warpv[lane] : -INFINITY;
            int   i3 = (lane < 8) ? warpi[lane] : 0x7fffffff;
            #pragma unroll
            for (int o = 4; o > 0; o >>= 1) {
                float v2 = __shfl_down_sync(0xffffffffu, v3, o);
                int   i2 = __shfl_down_sync(0xffffffffu, i3, o);
                if (v2 > v3 || (v2 == v3 && i2 < i3)) { v3 = v2; i3 = i2; }
            }
            if (lane == 0) { s_wini = i3; cand[sel] = i3; }
        }
        __syncthreads();
        int w = s_wini;
        if ((w & 255) == tid) {
            sv[w] = -INFINITY;
            bv = -INFINITY; bi = 0;
            #pragma unroll 4
            for (int j = 0; j < M_ / 256; ++j) {
                int i = tid + j * 256;
                float vv = sv[i];
                if (vv > bv) { bv = vv; bi = i; }
            }
        }
        __syncthreads();
    }

    for (int r8 = 0; r8 < 8; ++r8) {
        int c = r8 * 8 + warp;
        const float* mr = mem + (size_t)cand[c] * D_;
        float s = 0.f;
        #pragma unroll 8
        for (int j = lane; j < D_; j += 32) s += us[j] * mr[j];
        #pragma unroll
        for (int o = 16; o > 0; o >>= 1) s += __shfl_down_sync(0xffffffffu, s, o);
        if (lane == 0) scE[c] = s;
    }
    __syncthreads();

    if (warp == 0) {
        float v0 = scE[lane], v1 = scE[32 + lane];
        int   i0 = cand[lane], i1 = cand[32 + lane];
        for (int s = 0; s < KSEL; ++s) {
            float v; int ix, slot;
            if (v0 > v1 || (v0 == v1 && i0 < i1)) { v = v0; ix = i0; slot = lane; }
            else                                  { v = v1; ix = i1; slot = 32 + lane; }
            #pragma unroll
            for (int o = 16; o > 0; o >>= 1) {
                float v2 = __shfl_down_sync(0xffffffffu, v, o);
                int   x2 = __shfl_down_sync(0xffffffffu, ix, o);
                int   s2 = __shfl_down_sync(0xffffffffu, slot, o);
                if (v2 > v || (v2 == v && x2 < ix)) { v = v2; ix = x2; slot = s2; }
            }
            v    = __shfl_sync(0xffffffffu, v, 0);
            ix   = __shfl_sync(0xffffffffu, ix, 0);
            slot = __shfl_sync(0xffffffffu, slot, 0);
            if (slot == lane)      v0 = -INFINITY;
            if (slot == 32 + lane) v1 = -INFINITY;
            if (lane == 0) { pw[s] = v; pidx[s] = ix; }
        }
        if (lane == 0) {
            float mx = pw[0], ssum = 0.f;
            for (int k = 0; k < KSEL; ++k) {
                float e = expf((pw[k] - mx) * 0.0625f);
                pw[k] = e; ssum += e;
            }
            float inv = 1.f / ssum;
            for (int k = 0; k < KSEL; ++k) pw[k] *= inv;
        }
    }
    __syncthreads();

    for (int d = tid; d < D_; d += 256) {
        float acc = 0.f;
        #pragma unroll
        for (int k = 0; k < KSEL; ++k) acc += pw[k] * mem[(size_t)pidx[k] * D_ + d];
        z[(size_t)row * D_ + d] = acc;
    }
}

// ---------------- head: exact fp32 warp-per-output dot ------------------------
__global__ void head_kernel(const float* __restrict__ fus, const float* __restrict__ hw,
                            const float* __restrict__ hb, float* __restrict__ out)
{
    int gw = (blockIdx.x * blockDim.x + threadIdx.x) >> 5;
    int lane = threadIdx.x & 31;
    if (gw >= B_ * C_) return;
    int b = gw / C_, c = gw % C_;
    const float4* fr = (const float4*)(fus + (size_t)b * D_);
    const float4* wr = (const float4*)(hw + (size_t)c * D_);
    float s = 0.f;
    #pragma unroll 4
    for (int j = lane; j < D_ / 4; j += 32) {
        float4 f = fr[j], w = wr[j];
        s += f.x * w.x + f.y * w.y + f.z * w.z + f.w * w.w;
    }
    #pragma unroll
    for (int o = 16; o > 0; o >>= 1) s += __shfl_down_sync(0xffffffffu, s, o);
    if (lane == 0) out[b * C_ + c] = s + hb[c];
}

// ---------------- launch --------------------------------------------------------
extern "C" void kernel_launch(void* const* d_in, const int* in_sizes, int n_in,
                              void* d_out, int out_size)
{
    const float* x      = (const float*)d_in[0];
    const float* mem    = (const float*)d_in[2];
    const float* ff_w   = (const float*)d_in[3];
    const float* ff_b   = (const float*)d_in[4];
    const float* mp_w   = (const float*)d_in[5];
    const float* mp_b   = (const float*)d_in[6];
    const float* wq     = (const float*)d_in[7];
    const float* bq     = (const float*)d_in[8];
    const float* wk     = (const float*)d_in[9];
    const float* wv     = (const float*)d_in[11];
    const float* bv     = (const float*)d_in[12];
    const float* wo     = (const float*)d_in[13];
    const float* bo     = (const float*)d_in[14];
    const float* fuse_w = (const float*)d_in[15];
    const float* fuse_b = (const float*)d_in[16];
    const float* head_w = (const float*)d_in[17];
    const float* head_b = (const float*)d_in[18];
    float* out = (float*)d_out;

    float *xm, *q, *t, *u, *sc, *z, *y, *attn, *fin, *fus, *part, *wkT, *mpwT;
    __nv_bfloat16 *u_bf, *mem_bf;
    cudaGetSymbolAddress((void**)&xm,   g_xm);
    cudaGetSymbolAddress((void**)&q,    g_q);
    cudaGetSymbolAddress((void**)&t,    g_t);
    cudaGetSymbolAddress((void**)&u,    g_u);
    cudaGetSymbolAddress((void**)&sc,   g_sc);
    cudaGetSymbolAddress((void**)&z,    g_z);
    cudaGetSymbolAddress((void**)&y,    g_y);
    cudaGetSymbolAddress((void**)&attn, g_attn);
    cudaGetSymbolAddress((void**)&fin,  g_fin);
    cudaGetSymbolAddress((void**)&fus,  g_fus);
    cudaGetSymbolAddress((void**)&part, g_part);
    cudaGetSymbolAddress((void**)&wkT,  g_wkT);
    cudaGetSymbolAddress((void**)&mpwT, g_mpwT);
    cudaGetSymbolAddress((void**)&u_bf,   g_u_bf);
    cudaGetSymbolAddress((void**)&mem_bf, g_mem_bf);

    cudaFuncSetAttribute(bgemm3_kernel<3,8>, cudaFuncAttributeMaxDynamicSharedMemorySize, 65536);
    cudaFuncSetAttribute(bgemm3_kernel<3,2>, cudaFuncAttributeMaxDynamicSharedMemorySize, 65536);
    cudaFuncSetAttribute(bgemm3_kernel<3,1>, cudaFuncAttributeMaxDynamicSharedMemorySize, 65536);
    cudaFuncSetAttribute(bgemm3_kernel<1,2>, cudaFuncAttributeMaxDynamicSharedMemorySize, 32768);
    cudaFuncSetAttribute(bgemm3_kernel<1,4>, cudaFuncAttributeMaxDynamicSharedMemorySize, 32768);
    cudaFuncSetAttribute(bgemm3_kernel<1,8>, cudaFuncAttributeMaxDynamicSharedMemorySize, 32768);
    cudaFuncSetAttribute(bgemm_kernel, cudaFuncAttributeMaxDynamicSharedMemorySize, 98304);
    cudaFuncSetAttribute(topk_kernel, cudaFuncAttributeMaxDynamicSharedMemorySize, (M_ + D_) * 4);

    // prep: transposes + mem bf16
    transpose_kernel<<<dim3(64, 64), dim3(32, 8)>>>(wk, wkT);
    transpose_kernel<<<dim3(64, 64), dim3(32, 8)>>>(mp_w, mpwT);
    f2b_kernel<<<8192, 256>>>(mem, mem_bf, M_ * D_);

    // 1) xm
    mean_kernel<<<dim3(2, B_), 256>>>(x, xm);

    // 2) xf = xm@ff_w^T + ff_b -> fin[:, :D]
    bgemm3_kernel<3,8><<<dim3(16, 1, 8), 256, 65536>>>(
        xm, D_, 0, ff_w, D_, 0, part, D_, (long long)B_ * D_, nullptr, 0, B_, D_, D_);
    reduce_kernel<0,false><<<dim3(512, 1), 256>>>(
        part, fin, 2 * D_, 0, ff_b, 0, nullptr, B_ * D_, D_, 8);

    // 3) q = xf@wq^T + bq
    bgemm3_kernel<3,8><<<dim3(16, 1, 8), 256, 65536>>>(
        fin, 2 * D_, 0, wq, D_, 0, part, D_, (long long)B_ * D_, nullptr, 0, B_, D_, D_);
    reduce_kernel<0,false><<<dim3(512, 1), 256>>>(
        part, q, D_, 0, bq, 0, nullptr, B_ * D_, D_, 8);

    // 4) t = q_h @ wk_h   (TN via wkT), batched heads
    bgemm3_kernel<3,1><<<dim3(16, 1, H_), 256, 65536>>>(
        q, D_, DK_, wkT, D_, DK_, t, H_ * D_, D_, nullptr, 0, B_, D_, DK_);

    // 5) u = t @ mp_w  (TN via mpwT), split-K 2; reduce also emits u_bf
    bgemm3_kernel<3,2><<<dim3(16, 4, 2), 256, 65536>>>(
        t, D_, 0, mpwT, D_, 0, part, D_, (long long)B_ * H_ * D_,
        nullptr, 0, B_ * H_, D_, D_);
    reduce_kernel<0,true><<<dim3(4096, 1), 256>>>(
        part, u, D_, 0, nullptr, 0, u_bf, B_ * H_ * D_, D_, 2);

    // 6) scores = u @ mem^T  (bf16 TC, 3-stage)
    bgemm_kernel<<<dim3(M_ / 128, 4), 256, 98304>>>(
        u_bf, D_, mem_bf, D_, sc, M_, B_ * H_, M_, D_);

    // 7) topk -> z
    topk_kernel<<<B_ * H_, 256, (M_ + D_) * 4>>>(sc, u, mem, z);

    // 8) y = z @ mp_w^T + mp_b   (bf16, split-K 2)
    bgemm3_kernel<1,2><<<dim3(16, 4, 2), 256, 32768>>>(
        z, D_, 0, mp_w, D_, 0, part, D_, (long long)B_ * H_ * D_,
        nullptr, 0, B_ * H_, D_, D_);
    reduce_kernel<0,false><<<dim3(4096, 1), 256>>>(
        part, y, D_, 0, mp_b, 0, nullptr, B_ * H_ * D_, D_, 2);

    // 9) attn = y_h @ wv_h^T + bv_h  (bf16, heads batched, split-K 4)
    bgemm3_kernel<1,4><<<dim3(2, 1, H_ * 4), 256, 32768>>>(
        y, H_ * D_, D_, wv, D_, (long long)DK_ * D_, part, DK_, (long long)B_ * DK_,
        nullptr, 0, B_, DK_, D_);
    reduce_kernel<0,false><<<dim3(64, H_), 256>>>(
        part, attn, D_, DK_, bv, DK_, nullptr, B_ * DK_, DK_, 4);

    // 10) resp = attn @ wo^T + bo -> fin[:, D:]
    bgemm3_kernel<1,8><<<dim3(16, 1, 8), 256, 32768>>>(
        attn, D_, 0, wo, D_, 0, part, D_, (long long)B_ * D_, nullptr, 0, B_, D_, D_);
    reduce_kernel<0,false><<<dim3(512, 1), 256>>>(
        part, fin + D_, 2 * D_, 0, bo, 0, nullptr, B_ * D_, D_, 8);

    // 11) fus = gelu(fin @ fuse_w^T + fuse_b)
    bgemm3_kernel<3,8><<<dim3(16, 1, 8), 256, 65536>>>(
        fin, 2 * D_, 0, fuse_w, 2 * D_, 0, part, D_, (long long)B_ * D_,
        nullptr, 0, B_, D_, 2 * D_);
    reduce_kernel<1,false><<<dim3(512, 1), 256>>>(
        part, fus, D_, 0, fuse_b, 0, nullptr, B_ * D_, D_, 8);

    // 12) logits (exact fp32)
    head_kernel<<<(B_ * C_ * 32 + 255) / 256, 256>>>(fus, head_w, head_b, out);
}

// round 5
// speedup vs baseline: 8.5398x; 1.0376x over previous
#include <cuda_runtime.h>
#include <cuda_bf16.h>
#include <math.h>

#define B_  64
#define S_  196
#define D_  2048
#define H_  8
#define DK_ 256
#define M_  16384
#define KSEL 32
#define C_  29

__device__ float g_xm [B_ * D_];
__device__ float g_q  [B_ * D_];
__device__ float g_t  [B_ * H_ * D_];
__device__ float g_u  [B_ * H_ * D_];
__device__ float g_sc [B_ * H_ * M_];
__device__ float g_z  [B_ * H_ * D_];
__device__ float g_y  [B_ * H_ * D_];
__device__ float g_attn[B_ * D_];
__device__ float g_fin[B_ * 2 * D_];
__device__ float g_fus[B_ * D_];
__device__ float g_part[4 * 512 * 2048];
__device__ float g_wkT [D_ * D_];
__device__ float g_mpwT[D_ * D_];
__device__ __nv_bfloat16 g_u_bf [B_ * H_ * D_];
__device__ __nv_bfloat16 g_mem_bf[M_ * D_];

__device__ __forceinline__ float gelu_exact(float v) {
    return 0.5f * v * (1.0f + erff(v * 0.70710678118654752f));
}
__device__ __forceinline__ void split2(float a, float b, unsigned& hi, unsigned& lo) {
    __nv_bfloat162 h = __floats2bfloat162_rn(a, b);
    __nv_bfloat162 l = __floats2bfloat162_rn(a - __bfloat162float(h.x),
                                             b - __bfloat162float(h.y));
    hi = *(unsigned*)&h; lo = *(unsigned*)&l;
}

#define LDSM4(R, ADDR) asm volatile( \
    "ldmatrix.sync.aligned.m8n8.x4.shared.b16 {%0,%1,%2,%3}, [%4];" \
    : "=r"((R)[0]), "=r"((R)[1]), "=r"((R)[2]), "=r"((R)[3]) : "r"(ADDR))
#define MMA16816(D, A, B0, B1) asm volatile( \
    "mma.sync.aligned.m16n8k16.row.col.f32.bf16.bf16.f32 " \
    "{%0,%1,%2,%3},{%4,%5,%6,%7},{%8,%9},{%0,%1,%2,%3};" \
    : "+f"((D)[0]), "+f"((D)[1]), "+f"((D)[2]), "+f"((D)[3]) \
    : "r"((A)[0]), "r"((A)[1]), "r"((A)[2]), "r"((A)[3]), "r"(B0), "r"(B1))

// ---------------- transpose fp32 DxD ----------------
__global__ void transpose_kernel(const float* __restrict__ in, float* __restrict__ out) {
    __shared__ float tile[32][33];
    int x = blockIdx.x * 32 + threadIdx.x;
    #pragma unroll
    for (int j = threadIdx.y; j < 32; j += 8)
        tile[j][threadIdx.x] = __ldcs(&in[(size_t)(blockIdx.y * 32 + j) * D_ + x]);
    __syncthreads();
    int xo = blockIdx.y * 32 + threadIdx.x;
    #pragma unroll
    for (int j = threadIdx.y; j < 32; j += 8)
        out[(size_t)(blockIdx.x * 32 + j) * D_ + xo] = tile[threadIdx.x][j];
}

// ---------------- fp32 -> bf16, streaming, 16 elems/thread ----------------
__global__ void f2b_kernel(const float* __restrict__ a, __nv_bfloat16* __restrict__ o, int n) {
    int stride = gridDim.x * blockDim.x * 16;
    for (int i = (blockIdx.x * blockDim.x + threadIdx.x) * 16; i < n; i += stride) {
        float4 v0 = __ldcs((const float4*)(a + i));
        float4 v1 = __ldcs((const float4*)(a + i + 4));
        float4 v2 = __ldcs((const float4*)(a + i + 8));
        float4 v3 = __ldcs((const float4*)(a + i + 12));
        __nv_bfloat162 r[8];
        r[0] = __floats2bfloat162_rn(v0.x, v0.y);
        r[1] = __floats2bfloat162_rn(v0.z, v0.w);
        r[2] = __floats2bfloat162_rn(v1.x, v1.y);
        r[3] = __floats2bfloat162_rn(v1.z, v1.w);
        r[4] = __floats2bfloat162_rn(v2.x, v2.y);
        r[5] = __floats2bfloat162_rn(v2.z, v2.w);
        r[6] = __floats2bfloat162_rn(v3.x, v3.y);
        r[7] = __floats2bfloat162_rn(v3.z, v3.w);
        __stcs((uint4*)(o + i),     *(uint4*)&r[0]);
        __stcs((uint4*)(o + i + 8), *(uint4*)&r[4]);
    }
}

// ---------------- mean over S: two phase ----------------
#define SCHUNK 49
__global__ void mean1_kernel(const float* __restrict__ x, float* __restrict__ part) {
    int d4 = blockIdx.x * 256 + threadIdx.x;     // 0..511
    int b = blockIdx.y;
    int sc = blockIdx.z;                          // 0..3
    const float4* xp = (const float4*)(x + (size_t)b * S_ * D_) + (size_t)(sc * SCHUNK) * (D_ / 4) + d4;
    float4 s = make_float4(0.f, 0.f, 0.f, 0.f);
    #pragma unroll 7
    for (int i = 0; i < SCHUNK; ++i) {
        float4 v = __ldcs(xp + (size_t)i * (D_ / 4));
        s.x += v.x; s.y += v.y; s.z += v.z; s.w += v.w;
    }
    ((float4*)(part + ((size_t)sc * B_ + b) * D_))[d4] = s;
}
__global__ void mean2_kernel(const float* __restrict__ part, float* __restrict__ xm) {
    int i4 = blockIdx.x * 256 + threadIdx.x;     // over B_*D_/4
    const float4* p = (const float4*)part + i4;
    const int str = B_ * D_ / 4;
    float4 a = p[0], b = p[str], c = p[2 * str], d = p[3 * str];
    const float inv = 1.0f / S_;
    ((float4*)xm)[i4] = make_float4((a.x + b.x + c.x + d.x) * inv,
                                    (a.y + b.y + c.y + d.y) * inv,
                                    (a.z + b.z + c.z + d.z) * inv,
                                    (a.w + b.w + c.w + d.w) * inv);
}

// ---------------- unified TC TN GEMM, fp32 in/out, in-reg bf16 (hi/lo) --------
// C[M,N] = A[M,K] @ B[N,K]^T. NSPLIT 3 = hi/lo split; 1 = plain bf16.
// BM 128: warps 4x2 (64-wide N per warp); BM 64: warps 2x4 (32-wide N per warp).
template<int NSPLIT, int SPLITK, int BM>
__global__ __launch_bounds__(256) void bgemm3_kernel(
    const float* __restrict__ A, int lda, long long sAz,
    const float* __restrict__ Bm, int ldb, long long sBz,
    float* __restrict__ C, int ldc, long long sCz,
    const float* __restrict__ bias, int sbz,
    int M, int N, int K)
{
    extern __shared__ __nv_bfloat16 sm[];
    constexpr int APLANE = BM * 32;
    constexpr int LO_OFF = APLANE + 4096;                 // elems: hi block size
    constexpr int STAGE  = LO_OFF * ((NSPLIT == 3) ? 2 : 1);
    constexpr int N8     = (BM == 128) ? 8 : 4;           // n8 slots per warp
    const int tid = threadIdx.x, lane = tid & 31, warp = tid >> 5;
    const int warpM = (BM == 128) ? (warp >> 1) * 32 : (warp >> 2) * 32;
    const int warpN = (BM == 128) ? (warp & 1) * 64 : (warp & 3) * 32;
    const int m0 = blockIdx.y * BM, n0 = blockIdx.x * 128;
    const int zb = blockIdx.z / SPLITK, sk = blockIdx.z % SPLITK;
    const int Kc = K / SPLITK, k0base = sk * Kc;

    A  += (size_t)zb * sAz;
    Bm += (size_t)zb * sBz;
    C  += (size_t)blockIdx.z * sCz;

    const int cc = tid & 7, rr = tid >> 3;
    float4 ra[BM / 32], rb[4];
    unsigned sbase = (unsigned)__cvta_generic_to_shared(sm);

    float acc[2][N8][4];
    #pragma unroll
    for (int a = 0; a < 2; ++a)
        #pragma unroll
        for (int b = 0; b < N8; ++b)
            #pragma unroll
            for (int c = 0; c < 4; ++c) acc[a][b][c] = 0.f;

    auto ldg = [&](int kt) {
        int kcol = k0base + kt * 32 + cc * 4;
        #pragma unroll
        for (int j = 0; j < BM / 32; ++j) {
            int rA = m0 + j * 32 + rr;
            ra[j] = (rA < M) ? *(const float4*)(A + (size_t)rA * lda + kcol)
                             : make_float4(0.f, 0.f, 0.f, 0.f);
        }
        #pragma unroll
        for (int j = 0; j < 4; ++j) {
            int rB = n0 + j * 32 + rr;
            rb[j] = (rB < N) ? *(const float4*)(Bm + (size_t)rB * ldb + kcol)
                             : make_float4(0.f, 0.f, 0.f, 0.f);
        }
    };
    auto sts = [&](int s) {
        __nv_bfloat16* base = sm + s * STAGE;
        unsigned h0, h1, l0, l1;
        #pragma unroll
        for (int j = 0; j < BM / 32; ++j) {
            int row = j * 32 + rr;
            int off = row * 32 + ((((cc >> 1) ^ ((row >> 1) & 3)) << 3)) + ((cc & 1) << 2);
            split2(ra[j].x, ra[j].y, h0, l0);
            split2(ra[j].z, ra[j].w, h1, l1);
            *(uint2*)(base + off) = make_uint2(h0, h1);
            if (NSPLIT == 3) *(uint2*)(base + LO_OFF + off) = make_uint2(l0, l1);
        }
        #pragma unroll
        for (int j = 0; j < 4; ++j) {
            int row = j * 32 + rr;
            int off = APLANE + row * 32 + ((((cc >> 1) ^ ((row >> 1) & 3)) << 3)) + ((cc & 1) << 2);
            split2(rb[j].x, rb[j].y, h0, l0);
            split2(rb[j].z, rb[j].w, h1, l1);
            *(uint2*)(base + off) = make_uint2(h0, h1);
            if (NSPLIT == 3) *(uint2*)(base + LO_OFF + off) = make_uint2(l0, l1);
        }
    };
    auto compute = [&](int s) {
        unsigned aB = sbase + (unsigned)(s * STAGE) * 2u;
        unsigned bB = aB + (unsigned)APLANE * 2u;
        #pragma unroll
        for (int kk = 0; kk < 32; kk += 16) {
            unsigned ah[2][4], al[2][4];
            #pragma unroll
            for (int mi = 0; mi < 2; ++mi) {
                int row = warpM + mi * 16 + (lane & 15);
                int ch = (kk >> 3) + (lane >> 4);
                unsigned addr = aB +
                    (unsigned)(row * 32 + ((ch ^ ((row >> 1) & 3)) << 3)) * 2u;
                LDSM4(ah[mi], addr);
                if (NSPLIT == 3) LDSM4(al[mi], addr + (unsigned)LO_OFF * 2u);
            }
            unsigned bh[N8 / 2][4], bl[N8 / 2][4];
            #pragma unroll
            for (int ni = 0; ni < N8 / 2; ++ni) {
                int g = lane >> 3;
                int row = warpN + ni * 16 + ((g >> 1) << 3) + (lane & 7);
                int ch = (kk >> 3) + (g & 1);
                unsigned addr = bB +
                    (unsigned)(row * 32 + ((ch ^ ((row >> 1) & 3)) << 3)) * 2u;
                LDSM4(bh[ni], addr);
                if (NSPLIT == 3) LDSM4(bl[ni], addr + (unsigned)LO_OFF * 2u);
            }
            #pragma unroll
            for (int mi = 0; mi < 2; ++mi)
                #pragma unroll
                for (int n8 = 0; n8 < N8; ++n8) {
                    unsigned* hb = &bh[n8 >> 1][(n8 & 1) * 2];
                    MMA16816(acc[mi][n8], ah[mi], hb[0], hb[1]);
                    if (NSPLIT == 3) {
                        unsigned* lb = &bl[n8 >> 1][(n8 & 1) * 2];
                        MMA16816(acc[mi][n8], ah[mi], lb[0], lb[1]);
                        MMA16816(acc[mi][n8], al[mi], hb[0], hb[1]);
                    }
                }
        }
    };

    const int KT = Kc / 32;
    ldg(0);
    sts(0);
    __syncthreads();
    for (int t = 0; t < KT; ++t) {
        if (t + 1 < KT) ldg(t + 1);
        compute(t & 1);
        __syncthreads();
        if (t + 1 < KT) { sts((t + 1) & 1); __syncthreads(); }
    }

    #pragma unroll
    for (int mi = 0; mi < 2; ++mi) {
        int row = m0 + warpM + mi * 16 + (lane >> 2);
        #pragma unroll
        for (int n8 = 0; n8 < N8; ++n8) {
            int col = n0 + warpN + n8 * 8 + (lane & 3) * 2;
            float b0 = 0.f, b1 = 0.f;
            if (bias) { b0 = bias[zb * sbz + col]; b1 = bias[zb * sbz + col + 1]; }
            if (row < M)
                *(float2*)(C + (size_t)row * ldc + col) =
                    make_float2(acc[mi][n8][0] + b0, acc[mi][n8][1] + b1);
            if (row + 8 < M)
                *(float2*)(C + (size_t)(row + 8) * ldc + col) =
                    make_float2(acc[mi][n8][2] + b0, acc[mi][n8][3] + b1);
        }
    }
}

// ---------------- split-K reduce (+bias, +gelu, +bf16 mirror) ----------------
template<int EPI, bool WBF>
__global__ void reduce_kernel(const float* __restrict__ part, float* __restrict__ C,
                              int ldc, int cZ, const float* __restrict__ bias, int sbz,
                              __nv_bfloat16* __restrict__ Cbf,
                              int MN, int N, int SPLIT)
{
    int i = blockIdx.x * 256 + threadIdx.x;
    int z = blockIdx.y;
    if (i >= MN) return;
    const float* p = part + (size_t)z * SPLIT * MN + i;
    float s = 0.f;
    for (int k = 0; k < SPLIT; ++k) s += p[(size_t)k * MN];
    int n = i % N;
    if (bias) s += bias[z * sbz + n];
    if (EPI == 1) s = gelu_exact(s);
    C[(size_t)z * cZ + (size_t)(i / N) * ldc + n] = s;
    if (WBF) Cbf[(size_t)z * MN + i] = __float2bfloat16(s);
}

// ---------------- scores: bf16 TC TN GEMM, 3-stage cp.async -------------------
__device__ __forceinline__ unsigned bswz(int row, int chunk) {
    return (unsigned)(row * 64 + ((chunk ^ (row & 7)) * 8));
}
__global__ __launch_bounds__(256) void bgemm_kernel(
    const __nv_bfloat16* __restrict__ A, int lda,
    const __nv_bfloat16* __restrict__ B, int ldb,
    float* __restrict__ C, int ldc, int M, int N, int K)
{
    extern __shared__ __nv_bfloat16 sm[];
    const int tid = threadIdx.x, lane = tid & 31, warp = tid >> 5;
    const int warpM = (warp >> 1) * 32, warpN = (warp & 1) * 64;
    const int m0 = blockIdx.y * 128, n0 = blockIdx.x * 128;
    unsigned sbase = (unsigned)__cvta_generic_to_shared(sm);

    float acc[2][8][4];
    #pragma unroll
    for (int a = 0; a < 2; ++a)
        #pragma unroll
        for (int b = 0; b < 8; ++b)
            #pragma unroll
            for (int c = 0; c < 4; ++c) acc[a][b][c] = 0.f;

    const int cidx = tid & 7, rbase = tid >> 3;
    auto load_stage = [&](int s, int k0) {
        unsigned aB = sbase + (unsigned)s * 32768u;
        unsigned bB = aB + 16384u;
        #pragma unroll
        for (int j = 0; j < 4; ++j) {
            int r = j * 32 + rbase;
            const __nv_bfloat16* srcA = A + (size_t)(m0 + r) * lda + k0 + cidx * 8;
            int szA = (m0 + r < M) ? 16 : 0;
            asm volatile("cp.async.cg.shared.global [%0], [%1], 16, %2;\n"
                         :: "r"(aB + bswz(r, cidx) * 2u), "l"(srcA), "r"(szA));
            const __nv_bfloat16* srcB = B + (size_t)(n0 + r) * ldb + k0 + cidx * 8;
            asm volatile("cp.async.cg.shared.global [%0], [%1], 16, 16;\n"
                         :: "r"(bB + bswz(r, cidx) * 2u), "l"(srcB));
        }
        asm volatile("cp.async.commit_group;\n" ::);
    };
    auto compute = [&](int s) {
        unsigned aB = sbase + (unsigned)s * 32768u;
        unsigned bB = aB + 16384u;
        #pragma unroll
        for (int kk = 0; kk < 64; kk += 16) {
            unsigned af[2][4];
            #pragma unroll
            for (int mi = 0; mi < 2; ++mi) {
                int row = warpM + mi * 16 + (lane & 15);
                int ch = (kk >> 3) + (lane >> 4);
                LDSM4(af[mi], aB + bswz(row, ch) * 2u);
            }
            unsigned bf[4][4];
            #pragma unroll
            for (int ni = 0; ni < 4; ++ni) {
                int g = lane >> 3;
                int row = warpN + ni * 16 + ((g >> 1) << 3) + (lane & 7);
                int ch = (kk >> 3) + (g & 1);
                LDSM4(bf[ni], bB + bswz(row, ch) * 2u);
            }
            #pragma unroll
            for (int mi = 0; mi < 2; ++mi)
                #pragma unroll
                for (int n8 = 0; n8 < 8; ++n8) {
                    unsigned* bb = &bf[n8 >> 1][(n8 & 1) * 2];
                    MMA16816(acc[mi][n8], af[mi], bb[0], bb[1]);
                }
        }
    };

    const int KT = K >> 6;
    load_stage(0, 0);
    load_stage(1, 64);
    for (int t = 0; t < KT; ++t) {
        if (t + 2 < KT) {
            load_stage((t + 2) % 3, (t + 2) << 6);
            asm volatile("cp.async.wait_group 2;\n" ::);
        } else {
            asm volatile("cp.async.wait_group 0;\n" ::);
        }
        __syncthreads();
        compute(t % 3);
        __syncthreads();
    }

    #pragma unroll
    for (int mi = 0; mi < 2; ++mi) {
        int row = m0 + warpM + mi * 16 + (lane >> 2);
        #pragma unroll
        for (int n8 = 0; n8 < 8; ++n8) {
            int col = n0 + warpN + n8 * 8 + (lane & 3) * 2;
            if (row < M)
                *(float2*)(C + (size_t)row * ldc + col) =
                    make_float2(acc[mi][n8][0], acc[mi][n8][1]);
            if (row + 8 < M)
                *(float2*)(C + (size_t)(row + 8) * ldc + col) =
                    make_float2(acc[mi][n8][2], acc[mi][n8][3]);
        }
    }
}

// ---------------- top-64 coarse -> exact fp32 rescore -> top-32 + z ----------
__global__ __launch_bounds__(256) void topk_kernel(
    const float* __restrict__ scores, const float* __restrict__ u,
    const float* __restrict__ mem, float* __restrict__ z)
{
    extern __shared__ float dyn[];
    float* sv = dyn;
    float* us = dyn + M_;
    __shared__ float warpv[8];
    __shared__ int   warpi[8];
    __shared__ int   s_wini;
    __shared__ int   cand[64];
    __shared__ float scE[64];
    __shared__ float pw[KSEL];
    __shared__ int   pidx[KSEL];

    const int row = blockIdx.x, tid = threadIdx.x;
    const int lane = tid & 31, warp = tid >> 5;
    const float* sr = scores + (size_t)row * M_;
    const float* ur = u + (size_t)row * D_;

    float bv = -INFINITY; int bi = 0;
    #pragma unroll 4
    for (int j = 0; j < M_ / 256; ++j) {
        int i = tid + j * 256;
        float v = __ldcs(&sr[i]);
        sv[i] = v;
        if (v > bv) { bv = v; bi = i; }
    }
    for (int j = tid; j < D_; j += 256) us[j] = ur[j];
    __syncthreads();

    for (int sel = 0; sel < 64; ++sel) {
        float v = bv; int ix = bi;
        #pragma unroll
        for (int o = 16; o > 0; o >>= 1) {
            float v2 = __shfl_down_sync(0xffffffffu, v, o);
            int   i2 = __shfl_down_sync(0xffffffffu, ix, o);
            if (v2 > v || (v2 == v && i2 < ix)) { v = v2; ix = i2; }
        }
        if (lane == 0) { warpv[warp] = v; warpi[warp] = ix; }
        __syncthreads();
        if (warp == 0) {
            float v3 = (lane < 8) ? warpv[lane] : -INFINITY;
            int   i3 = (lane < 8) ? warpi[lane] : 0x7fffffff;
            #pragma unroll
            for (int o = 4; o > 0; o >>= 1) {
                float v2 = __shfl_down_sync(0xffffffffu, v3, o);
                int   i2 = __shfl_down_sync(0xffffffffu, i3, o);
                if (v2 > v3 || (v2 == v3 && i2 < i3)) { v3 = v2; i3 = i2; }
            }
            if (lane == 0) { s_wini = i3; cand[sel] = i3; }
        }
        __syncthreads();
        int w = s_wini;
        if ((w & 255) == tid) {
            sv[w] = -INFINITY;
            bv = -INFINITY; bi = 0;
            #pragma unroll 4
            for (int j = 0; j < M_ / 256; ++j) {
                int i = tid + j * 256;
                float vv = sv[i];
                if (vv > bv) { bv = vv; bi = i; }
            }
        }
        __syncthreads();
    }

    for (int r8 = 0; r8 < 8; ++r8) {
        int c = r8 * 8 + warp;
        const float* mr = mem + (size_t)cand[c] * D_;
        float s = 0.f;
        #pragma unroll 8
        for (int j = lane; j < D_; j += 32) s += us[j] * mr[j];
        #pragma unroll
        for (int o = 16; o > 0; o >>= 1) s += __shfl_down_sync(0xffffffffu, s, o);
        if (lane == 0) scE[c] = s;
    }
    __syncthreads();

    if (warp == 0) {
        float v0 = scE[lane], v1 = scE[32 + lane];
        int   i0 = cand[lane], i1 = cand[32 + lane];
        for (int s = 0; s < KSEL; ++s) {
            float v; int ix, slot;
            if (v0 > v1 || (v0 == v1 && i0 < i1)) { v = v0; ix = i0; slot = lane; }
            else                                  { v = v1; ix = i1; slot = 32 + lane; }
            #pragma unroll
            for (int o = 16; o > 0; o >>= 1) {
                float v2 = __shfl_down_sync(0xffffffffu, v, o);
                int   x2 = __shfl_down_sync(0xffffffffu, ix, o);
                int   s2 = __shfl_down_sync(0xffffffffu, slot, o);
                if (v2 > v || (v2 == v && x2 < ix)) { v = v2; ix = x2; slot = s2; }
            }
            v    = __shfl_sync(0xffffffffu, v, 0);
            ix   = __shfl_sync(0xffffffffu, ix, 0);
            slot = __shfl_sync(0xffffffffu, slot, 0);
            if (slot == lane)      v0 = -INFINITY;
            if (slot == 32 + lane) v1 = -INFINITY;
            if (lane == 0) { pw[s] = v; pidx[s] = ix; }
        }
        if (lane == 0) {
            float mx = pw[0], ssum = 0.f;
            for (int k = 0; k < KSEL; ++k) {
                float e = expf((pw[k] - mx) * 0.0625f);
                pw[k] = e; ssum += e;
            }
            float inv = 1.f / ssum;
            for (int k = 0; k < KSEL; ++k) pw[k] *= inv;
        }
    }
    __syncthreads();

    for (int d = tid; d < D_; d += 256) {
        float acc = 0.f;
        #pragma unroll
        for (int k = 0; k < KSEL; ++k) acc += pw[k] * mem[(size_t)pidx[k] * D_ + d];
        z[(size_t)row * D_ + d] = acc;
    }
}

// ---------------- head: exact fp32 warp-per-output dot ------------------------
__global__ void head_kernel(const float* __restrict__ fus, const float* __restrict__ hw,
                            const float* __restrict__ hb, float* __restrict__ out)
{
    int gw = (blockIdx.x * blockDim.x + threadIdx.x) >> 5;
    int lane = threadIdx.x & 31;
    if (gw >= B_ * C_) return;
    int b = gw / C_, c = gw % C_;
    const float4* fr = (const float4*)(fus + (size_t)b * D_);
    const float4* wr = (const float4*)(hw + (size_t)c * D_);
    float s = 0.f;
    #pragma unroll 4
    for (int j = lane; j < D_ / 4; j += 32) {
        float4 f = fr[j], w = wr[j];
        s += f.x * w.x + f.y * w.y + f.z * w.z + f.w * w.w;
    }
    #pragma unroll
    for (int o = 16; o > 0; o >>= 1) s += __shfl_down_sync(0xffffffffu, s, o);
    if (lane == 0) out[b * C_ + c] = s + hb[c];
}

// ---------------- launch --------------------------------------------------------
extern "C" void kernel_launch(void* const* d_in, const int* in_sizes, int n_in,
                              void* d_out, int out_size)
{
    const float* x      = (const float*)d_in[0];
    const float* mem    = (const float*)d_in[2];
    const float* ff_w   = (const float*)d_in[3];
    const float* ff_b   = (const float*)d_in[4];
    const float* mp_w   = (const float*)d_in[5];
    const float* mp_b   = (const float*)d_in[6];
    const float* wq     = (const float*)d_in[7];
    const float* bq     = (const float*)d_in[8];
    const float* wk     = (const float*)d_in[9];
    const float* wv     = (const float*)d_in[11];
    const float* bv     = (const float*)d_in[12];
    const float* wo     = (const float*)d_in[13];
    const float* bo     = (const float*)d_in[14];
    const float* fuse_w = (const float*)d_in[15];
    const float* fuse_b = (const float*)d_in[16];
    const float* head_w = (const float*)d_in[17];
    const float* head_b = (const float*)d_in[18];
    float* out = (float*)d_out;

    float *xm, *q, *t, *u, *sc, *z, *y, *attn, *fin, *fus, *part, *wkT, *mpwT;
    __nv_bfloat16 *u_bf, *mem_bf;
    cudaGetSymbolAddress((void**)&xm,   g_xm);
    cudaGetSymbolAddress((void**)&q,    g_q);
    cudaGetSymbolAddress((void**)&t,    g_t);
    cudaGetSymbolAddress((void**)&u,    g_u);
    cudaGetSymbolAddress((void**)&sc,   g_sc);
    cudaGetSymbolAddress((void**)&z,    g_z);
    cudaGetSymbolAddress((void**)&y,    g_y);
    cudaGetSymbolAddress((void**)&attn, g_attn);
    cudaGetSymbolAddress((void**)&fin,  g_fin);
    cudaGetSymbolAddress((void**)&fus,  g_fus);
    cudaGetSymbolAddress((void**)&part, g_part);
    cudaGetSymbolAddress((void**)&wkT,  g_wkT);
    cudaGetSymbolAddress((void**)&mpwT, g_mpwT);
    cudaGetSymbolAddress((void**)&u_bf,   g_u_bf);
    cudaGetSymbolAddress((void**)&mem_bf, g_mem_bf);

    cudaFuncSetAttribute(bgemm3_kernel<3,8,64>,  cudaFuncAttributeMaxDynamicSharedMemorySize, 49152);
    cudaFuncSetAttribute(bgemm3_kernel<3,1,64>,  cudaFuncAttributeMaxDynamicSharedMemorySize, 49152);
    cudaFuncSetAttribute(bgemm3_kernel<3,2,128>, cudaFuncAttributeMaxDynamicSharedMemorySize, 65536);
    cudaFuncSetAttribute(bgemm3_kernel<1,2,128>, cudaFuncAttributeMaxDynamicSharedMemorySize, 32768);
    cudaFuncSetAttribute(bgemm3_kernel<1,4,64>,  cudaFuncAttributeMaxDynamicSharedMemorySize, 24576);
    cudaFuncSetAttribute(bgemm3_kernel<1,8,64>,  cudaFuncAttributeMaxDynamicSharedMemorySize, 24576);
    cudaFuncSetAttribute(bgemm_kernel, cudaFuncAttributeMaxDynamicSharedMemorySize, 98304);
    cudaFuncSetAttribute(topk_kernel, cudaFuncAttributeMaxDynamicSharedMemorySize, (M_ + D_) * 4);

    // prep: transposes + mem bf16
    transpose_kernel<<<dim3(64, 64), dim3(32, 8)>>>(wk, wkT);
    transpose_kernel<<<dim3(64, 64), dim3(32, 8)>>>(mp_w, mpwT);
    f2b_kernel<<<8192, 256>>>(mem, mem_bf, M_ * D_);

    // 1) xm (two-phase)
    mean1_kernel<<<dim3(2, B_, 4), 256>>>(x, part);
    mean2_kernel<<<B_ * D_ / 1024, 256>>>(part, xm);

    // 2) xf = xm@ff_w^T + ff_b -> fin[:, :D]
    bgemm3_kernel<3,8,64><<<dim3(16, 1, 8), 256, 49152>>>(
        xm, D_, 0, ff_w, D_, 0, part, D_, (long long)B_ * D_, nullptr, 0, B_, D_, D_);
    reduce_kernel<0,false><<<dim3(512, 1), 256>>>(
        part, fin, 2 * D_, 0, ff_b, 0, nullptr, B_ * D_, D_, 8);

    // 3) q = xf@wq^T + bq
    bgemm3_kernel<3,8,64><<<dim3(16, 1, 8), 256, 49152>>>(
        fin, 2 * D_, 0, wq, D_, 0, part, D_, (long long)B_ * D_, nullptr, 0, B_, D_, D_);
    reduce_kernel<0,false><<<dim3(512, 1), 256>>>(
        part, q, D_, 0, bq, 0, nullptr, B_ * D_, D_, 8);

    // 4) t = q_h @ wk_h   (TN via wkT), batched heads
    bgemm3_kernel<3,1,64><<<dim3(16, 1, H_), 256, 49152>>>(
        q, D_, DK_, wkT, D_, DK_, t, H_ * D_, D_, nullptr, 0, B_, D_, DK_);

    // 5) u = t @ mp_w  (TN via mpwT), split-K 2; reduce also emits u_bf
    bgemm3_kernel<3,2,128><<<dim3(16, 4, 2), 256, 65536>>>(
        t, D_, 0, mpwT, D_, 0, part, D_, (long long)B_ * H_ * D_,
        nullptr, 0, B_ * H_, D_, D_);
    reduce_kernel<0,true><<<dim3(4096, 1), 256>>>(
        part, u, D_, 0, nullptr, 0, u_bf, B_ * H_ * D_, D_, 2);

    // 6) scores = u @ mem^T  (bf16 TC, 3-stage)
    bgemm_kernel<<<dim3(M_ / 128, 4), 256, 98304>>>(
        u_bf, D_, mem_bf, D_, sc, M_, B_ * H_, M_, D_);

    // 7) topk -> z
    topk_kernel<<<B_ * H_, 256, (M_ + D_) * 4>>>(sc, u, mem, z);

    // 8) y = z @ mp_w^T + mp_b   (bf16, split-K 2)
    bgemm3_kernel<1,2,128><<<dim3(16, 4, 2), 256, 32768>>>(
        z, D_, 0, mp_w, D_, 0, part, D_, (long long)B_ * H_ * D_,
        nullptr, 0, B_ * H_, D_, D_);
    reduce_kernel<0,false><<<dim3(4096, 1), 256>>>(
        part, y, D_, 0, mp_b, 0, nullptr, B_ * H_ * D_, D_, 2);

    // 9) attn = y_h @ wv_h^T + bv_h  (bf16, heads batched, split-K 4)
    bgemm3_kernel<1,4,64><<<dim3(2, 1, H_ * 4), 256, 24576>>>(
        y, H_ * D_, D_, wv, D_, (long long)DK_ * D_, part, DK_, (long long)B_ * DK_,
        nullptr, 0, B_, DK_, D_);
    reduce_kernel<0,false><<<dim3(64, H_), 256>>>(
        part, attn, D_, DK_, bv, DK_, nullptr, B_ * DK_, DK_, 4);

    // 10) resp = attn @ wo^T + bo -> fin[:, D:]
    bgemm3_kernel<1,8,64><<<dim3(16, 1, 8), 256, 24576>>>(
        attn, D_, 0, wo, D_, 0, part, D_, (long long)B_ * D_, nullptr, 0, B_, D_, D_);
    reduce_kernel<0,false><<<dim3(512, 1), 256>>>(
        part, fin + D_, 2 * D_, 0, bo, 0, nullptr, B_ * D_, D_, 8);

    // 11) fus = gelu(fin @ fuse_w^T + fuse_b)
    bgemm3_kernel<3,8,64><<<dim3(16, 1, 8), 256, 49152>>>(
        fin, 2 * D_, 0, fuse_w, 2 * D_, 0, part, D_, (long long)B_ * D_,
        nullptr, 0, B_, D_, 2 * D_);
    reduce_kernel<1,false><<<dim3(512, 1), 256>>>(
        part, fus, D_, 0, fuse_b, 0, nullptr, B_ * D_, D_, 8);

    // 12) logits (exact fp32)
    head_kernel<<<(B_ * C_ * 32 + 255) / 256, 256>>>(fus, head_w, head_b, out);
}